// round 1
// baseline (speedup 1.0000x reference)
#include <cuda_runtime.h>
#include <cuda_bf16.h>
#include <cstdint>

// Problem constants
#define BB 8
#define TT 512
#define DD 1024
#define HH 16
#define DH 64

// Intermediates as device globals (no allocation allowed)
__device__ float g_Q[BB * HH * TT * DH];   // [BH, T, DH]
__device__ float g_K[BB * HH * TT * DH];
__device__ float g_V[BB * HH * TT * DH];
__device__ float g_O[BB * TT * DD];        // [B*T, D] attention output (heads concat)

// ---------------------------------------------------------------------------
// Kernel 1: per-head Q/K/V projections
// grid: (T/64, B*H), block: 256
// ---------------------------------------------------------------------------
__global__ void qkv_kernel(const float* __restrict__ X,
                           const float* __restrict__ Wq, const float* __restrict__ bq,
                           const float* __restrict__ Wk, const float* __restrict__ bk,
                           const float* __restrict__ Wv, const float* __restrict__ bv)
{
    __shared__ float Xs[64][65];
    __shared__ float Ws[64][65];

    int bh = blockIdx.y;
    int b  = bh >> 4;       // / H
    int h  = bh & 15;       // % H
    int t0 = blockIdx.x * 64;
    int tid = threadIdx.x;

    // load X tile: Xs[r][d] = X[b, t0+r, h*DH + d]
    for (int i = tid; i < 64 * 64; i += 256) {
        int r = i >> 6, d = i & 63;
        Xs[r][d] = X[((size_t)(b * TT + t0 + r)) * DD + h * DH + d];
    }

    const float* Wlist[3] = {Wq, Wk, Wv};
    const float* blist[3] = {bq, bk, bv};
    float* Olist[3] = {g_Q, g_K, g_V};

    int c  = tid & 63;
    int r0 = tid >> 6;      // 0..3

    for (int p = 0; p < 3; p++) {
        __syncthreads();  // Xs ready (p=0); prior compute done before Ws overwrite (p>0)
        const float* W = Wlist[p] + h * DH * DH;
        for (int i = tid; i < 64 * 64; i += 256) {
            int d = i >> 6, e = i & 63;
            Ws[d][e] = W[i];
        }
        __syncthreads();

        float bias = blist[p][h * DH + c];
        float* O = Olist[p] + ((size_t)bh * TT + t0) * DH;
        for (int rr = 0; rr < 16; rr++) {
            int r = r0 * 16 + rr;
            float acc = bias;
            #pragma unroll
            for (int d = 0; d < 64; d++)
                acc += Xs[r][d] * Ws[d][c];
            O[r * DH + c] = acc;
        }
    }
}

// ---------------------------------------------------------------------------
// Kernel 2: flash-style attention, online softmax.
// grid: (T/64, B*H), block: 256.  thread = (q = tid>>2, quad = tid&3).
// Each thread holds the full 64-dim Q row in regs, computes S for 16 keys,
// exchanges P via width-4 shuffles, accumulates 16 output dims.
// ---------------------------------------------------------------------------
__global__ void attn_kernel(const int* __restrict__ mask, float* __restrict__ O)
{
    __shared__ float Ks[64][68];   // pad 68 -> 272B rows, float4 aligned
    __shared__ float Vs[64][68];

    int bh = blockIdx.y;
    int b  = bh >> 4;
    int h  = bh & 15;
    int q0 = blockIdx.x * 64;
    int tid = threadIdx.x;
    int q    = tid >> 2;    // 0..63
    int quad = tid & 3;     // 0..3

    // load my full Q row into registers
    const float* Qb = g_Q + ((size_t)bh * TT + q0 + q) * DH;
    float qreg[64];
    #pragma unroll
    for (int j = 0; j < 64; j += 4) {
        float4 v = *reinterpret_cast<const float4*>(Qb + j);
        qreg[j] = v.x; qreg[j+1] = v.y; qreg[j+2] = v.z; qreg[j+3] = v.w;
    }

    float m = -1e30f, l = 0.0f;
    float o[16];
    #pragma unroll
    for (int j = 0; j < 16; j++) o[j] = 0.0f;

    const int* mrow = mask + b * TT;

    for (int kt = 0; kt < TT; kt += 64) {
        const float* Kb = g_K + ((size_t)bh * TT + kt) * DH;
        const float* Vb = g_V + ((size_t)bh * TT + kt) * DH;
        // load K/V tiles (1024 float4 each, 4 per thread per array)
        for (int i = tid; i < 1024; i += 256) {
            int r = i >> 4, c4 = (i & 15) * 4;
            *reinterpret_cast<float4*>(&Ks[r][c4]) =
                *reinterpret_cast<const float4*>(Kb + r * 64 + c4);
            *reinterpret_cast<float4*>(&Vs[r][c4]) =
                *reinterpret_cast<const float4*>(Vb + r * 64 + c4);
        }
        __syncthreads();

        // S for my 16 keys
        float s[16];
        #pragma unroll
        for (int kk = 0; kk < 16; kk++) {
            int k = quad * 16 + kk;
            float acc = 0.0f;
            const float* Kr = &Ks[k][0];
            #pragma unroll
            for (int j = 0; j < 64; j++)
                acc += qreg[j] * Kr[j];
            acc *= 0.125f;   // 1/sqrt(64)
            s[kk] = (mrow[kt + k] > 0) ? acc : -1e9f;
        }

        // row max across 64 keys (16 local + quad shuffle)
        float mx = s[0];
        #pragma unroll
        for (int kk = 1; kk < 16; kk++) mx = fmaxf(mx, s[kk]);
        mx = fmaxf(mx, __shfl_xor_sync(0xffffffffu, mx, 1, 4));
        mx = fmaxf(mx, __shfl_xor_sync(0xffffffffu, mx, 2, 4));
        float mnew  = fmaxf(m, mx);
        float alpha = __expf(m - mnew);

        float rs = 0.0f;
        #pragma unroll
        for (int kk = 0; kk < 16; kk++) {
            s[kk] = __expf(s[kk] - mnew);
            rs += s[kk];
        }
        rs += __shfl_xor_sync(0xffffffffu, rs, 1, 4);
        rs += __shfl_xor_sync(0xffffffffu, rs, 2, 4);
        l = l * alpha + rs;
        m = mnew;

        #pragma unroll
        for (int j = 0; j < 16; j++) o[j] *= alpha;

        // P @ V : broadcast p over the quad group via width-4 shuffles
        #pragma unroll
        for (int src = 0; src < 4; src++) {
            #pragma unroll
            for (int kk = 0; kk < 16; kk++) {
                float p = __shfl_sync(0xffffffffu, s[kk], src, 4);
                const float* Vr = &Vs[src * 16 + kk][quad * 16];
                #pragma unroll
                for (int j = 0; j < 16; j++)
                    o[j] += p * Vr[j];
            }
        }
        __syncthreads();  // before next tile overwrite
    }

    float inv = 1.0f / l;
    // write in concatenated-head layout: O[b, t, h*DH + e]
    float* Ob = O + ((size_t)(b * TT + q0 + q)) * DD + h * DH + quad * 16;
    #pragma unroll
    for (int j = 0; j < 16; j++)
        Ob[j] = o[j] * inv;
}

// ---------------------------------------------------------------------------
// Kernel 3: fusion GEMM  C[4096,1024] = A[4096,1024] @ Wf[1024,1024] + bf
// 64x64 block tile, 256 threads, 4x4 microtile, k-step 16.
// ---------------------------------------------------------------------------
__global__ void fuse_kernel(const float* __restrict__ Wf, const float* __restrict__ bf,
                            float* __restrict__ C)
{
    __shared__ float As[16][65];   // [k][m]
    __shared__ float Bs[16][65];   // [k][n]

    int tid = threadIdx.x;
    int tx = tid & 15;        // n group
    int ty = tid >> 4;        // m group
    int m0 = blockIdx.y * 64;
    int n0 = blockIdx.x * 64;

    const float* A = g_O;
    float acc[4][4];
    #pragma unroll
    for (int i = 0; i < 4; i++)
        #pragma unroll
        for (int j = 0; j < 4; j++) acc[i][j] = 0.0f;

    for (int k0 = 0; k0 < 1024; k0 += 16) {
        for (int i = tid; i < 1024; i += 256) {
            int mm = i >> 4, kk = i & 15;
            As[kk][mm] = A[(size_t)(m0 + mm) * 1024 + k0 + kk];
        }
        for (int i = tid; i < 1024; i += 256) {
            int kk = i >> 6, nn = i & 63;
            Bs[kk][nn] = Wf[(size_t)(k0 + kk) * 1024 + n0 + nn];
        }
        __syncthreads();

        #pragma unroll
        for (int kk = 0; kk < 16; kk++) {
            float a[4], bb[4];
            #pragma unroll
            for (int i = 0; i < 4; i++) a[i]  = As[kk][ty * 4 + i];
            #pragma unroll
            for (int j = 0; j < 4; j++) bb[j] = Bs[kk][tx * 4 + j];
            #pragma unroll
            for (int i = 0; i < 4; i++)
                #pragma unroll
                for (int j = 0; j < 4; j++)
                    acc[i][j] += a[i] * bb[j];
        }
        __syncthreads();
    }

    #pragma unroll
    for (int i = 0; i < 4; i++) {
        int mm = m0 + ty * 4 + i;
        #pragma unroll
        for (int j = 0; j < 4; j++) {
            int nn = n0 + tx * 4 + j;
            C[(size_t)mm * 1024 + nn] = acc[i][j] + bf[nn];
        }
    }
}

// ---------------------------------------------------------------------------
extern "C" void kernel_launch(void* const* d_in, const int* in_sizes, int n_in,
                              void* d_out, int out_size)
{
    const float* X    = (const float*)d_in[0];
    const int*   mask = (const int*)  d_in[1];
    const float* Wq   = (const float*)d_in[2];
    const float* bq   = (const float*)d_in[3];
    const float* Wk   = (const float*)d_in[4];
    const float* bk   = (const float*)d_in[5];
    const float* Wv   = (const float*)d_in[6];
    const float* bv   = (const float*)d_in[7];
    const float* Wf   = (const float*)d_in[8];
    const float* bf   = (const float*)d_in[9];
    float* out = (float*)d_out;

    float* g_O_ptr = nullptr;
    cudaGetSymbolAddress((void**)&g_O_ptr, g_O);

    dim3 grid1(TT / 64, BB * HH);
    qkv_kernel<<<grid1, 256>>>(X, Wq, bq, Wk, bk, Wv, bv);

    dim3 grid2(TT / 64, BB * HH);
    attn_kernel<<<grid2, 256>>>(mask, g_O_ptr);

    dim3 grid3(DD / 64, (BB * TT) / 64);
    fuse_kernel<<<grid3, 256>>>(Wf, bf, out);
}

// round 2
// speedup vs baseline: 3.4925x; 3.4925x over previous
#include <cuda_runtime.h>
#include <cuda_bf16.h>
#include <cstdint>

#define BB 8
#define TT 512
#define DD 1024
#define HH 16
#define DH 64

// Intermediates (device globals; no allocs allowed).
// Q/K/V stored TRANSPOSED per head: [bh][d(64)][t(512)]
__device__ float g_Q[BB * HH * DH * TT];
__device__ float g_K[BB * HH * DH * TT];
__device__ float g_V[BB * HH * DH * TT];
// attention output, natural concat layout [B*T][D]
__device__ float g_O[BB * TT * DD];

// ---------------------------------------------------------------------------
// Kernel 1: QKV projections. grid (T/64, B*H), 256 threads.
// tile: 64 t x 64 e. micro: thread (tn,tm): t = tn+16i (i<4), e = tm*4+j (j<4).
// Xs stored k-major [d][t] (pad 65), Ws [d][e] natural.
// Outputs written transposed [e][t] -> coalesced along t.
// ---------------------------------------------------------------------------
__global__ __launch_bounds__(256) void qkv_kernel(
    const float* __restrict__ X,
    const float* __restrict__ Wq, const float* __restrict__ bq,
    const float* __restrict__ Wk, const float* __restrict__ bk,
    const float* __restrict__ Wv, const float* __restrict__ bv)
{
    __shared__ float Xs[64 * 65];
    __shared__ float Ws[64 * 64];

    int bh = blockIdx.y;
    int b  = bh >> 4;
    int h  = bh & 15;
    int t0 = blockIdx.x * 64;
    int tid = threadIdx.x;
    int tn = tid & 15;
    int tm = tid >> 4;

    // load X tile transposed: Xs[d][t] <- X[b, t0+t, h*64+d]
    const float* Xb = X + ((size_t)(b * TT + t0)) * DD + h * DH;
    for (int i = tid; i < 1024; i += 256) {
        int t = i >> 4, d4 = (i & 15) * 4;
        float4 v = *reinterpret_cast<const float4*>(Xb + (size_t)t * DD + d4);
        Xs[(d4 + 0) * 65 + t] = v.x;
        Xs[(d4 + 1) * 65 + t] = v.y;
        Xs[(d4 + 2) * 65 + t] = v.z;
        Xs[(d4 + 3) * 65 + t] = v.w;
    }

    const float* Wl[3] = {Wq, Wk, Wv};
    const float* bl[3] = {bq, bk, bv};
    float* Ol[3];
    Ol[0] = g_Q; Ol[1] = g_K; Ol[2] = g_V;

    for (int p = 0; p < 3; p++) {
        __syncthreads();   // prior compute done (and Xs ready at p=0)
        const float* W = Wl[p] + h * DH * DH;
        for (int i = tid; i < 1024; i += 256) {
            int d = i >> 4, e4 = (i & 15) * 4;
            *reinterpret_cast<float4*>(&Ws[d * 64 + e4]) =
                *reinterpret_cast<const float4*>(W + d * 64 + e4);
        }
        __syncthreads();

        float acc[4][4];
        #pragma unroll
        for (int j = 0; j < 4; j++)
            #pragma unroll
            for (int i = 0; i < 4; i++) acc[j][i] = 0.0f;

        #pragma unroll 8
        for (int d = 0; d < 64; d++) {
            float a[4], bb[4];
            #pragma unroll
            for (int j = 0; j < 4; j++) a[j] = Ws[d * 64 + tm * 4 + j];
            #pragma unroll
            for (int i = 0; i < 4; i++) bb[i] = Xs[d * 65 + tn + 16 * i];
            #pragma unroll
            for (int j = 0; j < 4; j++)
                #pragma unroll
                for (int i = 0; i < 4; i++)
                    acc[j][i] += a[j] * bb[i];
        }

        const float* bias = bl[p] + h * DH;
        float* O = Ol[p] + (size_t)bh * DH * TT;   // [e][t]
        #pragma unroll
        for (int j = 0; j < 4; j++) {
            int e = tm * 4 + j;
            float be = bias[e];
            #pragma unroll
            for (int i = 0; i < 4; i++)
                O[(size_t)e * TT + t0 + tn + 16 * i] = acc[j][i] + be;
        }
    }
}

// ---------------------------------------------------------------------------
// Kernel 2: flash attention. grid (T/128, B*H), 256 threads, dynamic smem.
// tile: 128 q x 64 k. micro: q = tm+16i (i<8), k/d = tn+16j (j<4).
// ---------------------------------------------------------------------------
#define QS_OFF 0                       // [64][128]  floats
#define KS_OFF (QS_OFF + 64 * 128)     // [64][64]
#define VS_OFF (KS_OFF + 64 * 64)      // [64][65]   (transpose-loaded, pad)
#define PS_OFF (VS_OFF + 64 * 65)      // [64][129]  (pad)
#define MS_OFF (PS_OFF + 64 * 129)     // 512 ints
#define ATTN_SMEM ((MS_OFF + 512) * 4)

__global__ __launch_bounds__(256, 2) void attn_kernel(const int* __restrict__ mask)
{
    extern __shared__ float sm[];
    float* sQ = sm + QS_OFF;
    float* sK = sm + KS_OFF;
    float* sV = sm + VS_OFF;
    float* sP = sm + PS_OFF;
    int*   sM = (int*)(sm + MS_OFF);

    int bh = blockIdx.y;
    int b  = bh >> 4;
    int h  = bh & 15;
    int q0 = blockIdx.x * 128;
    int tid = threadIdx.x;
    int tn = tid & 15;
    int tm = tid >> 4;

    const float* Qg = g_Q + (size_t)bh * DH * TT;
    const float* Kg = g_K + (size_t)bh * DH * TT;
    const float* Vg = g_V + (size_t)bh * DH * TT;

    // Qs[d][q] direct copy from transposed global
    for (int i = tid; i < 2048; i += 256) {
        int d = i >> 5, q4 = (i & 31) * 4;
        *reinterpret_cast<float4*>(&sQ[d * 128 + q4]) =
            *reinterpret_cast<const float4*>(Qg + (size_t)d * TT + q0 + q4);
    }
    for (int i = tid; i < TT; i += 256) sM[i] = mask[b * TT + i];
    __syncthreads();

    float m_[8], l_[8], O[8][4];
    #pragma unroll
    for (int i = 0; i < 8; i++) {
        m_[i] = -1e30f; l_[i] = 0.0f;
        #pragma unroll
        for (int j = 0; j < 4; j++) O[i][j] = 0.0f;
    }

    for (int kt = 0; kt < TT; kt += 64) {
        // Ks[d][k] direct copy
        for (int i = tid; i < 1024; i += 256) {
            int d = i >> 4, k4 = (i & 15) * 4;
            *reinterpret_cast<float4*>(&sK[d * 64 + k4]) =
                *reinterpret_cast<const float4*>(Kg + (size_t)d * TT + kt + k4);
        }
        // Vs[k][d] transpose-load from [d][t]
        for (int i = tid; i < 1024; i += 256) {
            int d = i >> 4, k4 = (i & 15) * 4;
            float4 v = *reinterpret_cast<const float4*>(Vg + (size_t)d * TT + kt + k4);
            sV[(k4 + 0) * 65 + d] = v.x;
            sV[(k4 + 1) * 65 + d] = v.y;
            sV[(k4 + 2) * 65 + d] = v.z;
            sV[(k4 + 3) * 65 + d] = v.w;
        }
        __syncthreads();

        // S = Q^T K
        float S[8][4];
        #pragma unroll
        for (int i = 0; i < 8; i++)
            #pragma unroll
            for (int j = 0; j < 4; j++) S[i][j] = 0.0f;

        #pragma unroll 4
        for (int d = 0; d < 64; d++) {
            float a[8], bb[4];
            #pragma unroll
            for (int i = 0; i < 8; i++) a[i] = sQ[d * 128 + tm + 16 * i];
            #pragma unroll
            for (int j = 0; j < 4; j++) bb[j] = sK[d * 64 + tn + 16 * j];
            #pragma unroll
            for (int i = 0; i < 8; i++)
                #pragma unroll
                for (int j = 0; j < 4; j++)
                    S[i][j] += a[i] * bb[j];
        }

        int mk[4];
        #pragma unroll
        for (int j = 0; j < 4; j++) mk[j] = sM[kt + tn + 16 * j];
        #pragma unroll
        for (int i = 0; i < 8; i++)
            #pragma unroll
            for (int j = 0; j < 4; j++)
                S[i][j] = (mk[j] > 0) ? S[i][j] * 0.125f : -1e9f;

        // online softmax (rows across 16 tn lanes)
        #pragma unroll
        for (int i = 0; i < 8; i++) {
            float mx = S[i][0];
            #pragma unroll
            for (int j = 1; j < 4; j++) mx = fmaxf(mx, S[i][j]);
            mx = fmaxf(mx, __shfl_xor_sync(0xffffffffu, mx, 1, 16));
            mx = fmaxf(mx, __shfl_xor_sync(0xffffffffu, mx, 2, 16));
            mx = fmaxf(mx, __shfl_xor_sync(0xffffffffu, mx, 4, 16));
            mx = fmaxf(mx, __shfl_xor_sync(0xffffffffu, mx, 8, 16));
            float mnew  = fmaxf(m_[i], mx);
            float alpha = __expf(m_[i] - mnew);
            float rs = 0.0f;
            #pragma unroll
            for (int j = 0; j < 4; j++) {
                S[i][j] = __expf(S[i][j] - mnew);
                rs += S[i][j];
            }
            rs += __shfl_xor_sync(0xffffffffu, rs, 1, 16);
            rs += __shfl_xor_sync(0xffffffffu, rs, 2, 16);
            rs += __shfl_xor_sync(0xffffffffu, rs, 4, 16);
            rs += __shfl_xor_sync(0xffffffffu, rs, 8, 16);
            l_[i] = l_[i] * alpha + rs;
            m_[i] = mnew;
            #pragma unroll
            for (int j = 0; j < 4; j++) O[i][j] *= alpha;
        }

        // publish P[k][q]
        #pragma unroll
        for (int i = 0; i < 8; i++)
            #pragma unroll
            for (int j = 0; j < 4; j++)
                sP[(tn + 16 * j) * 129 + tm + 16 * i] = S[i][j];
        __syncthreads();

        // O += P V
        #pragma unroll 4
        for (int kk = 0; kk < 64; kk++) {
            float ap[8], bv[4];
            #pragma unroll
            for (int i = 0; i < 8; i++) ap[i] = sP[kk * 129 + tm + 16 * i];
            #pragma unroll
            for (int j = 0; j < 4; j++) bv[j] = sV[kk * 65 + tn + 16 * j];
            #pragma unroll
            for (int i = 0; i < 8; i++)
                #pragma unroll
                for (int j = 0; j < 4; j++)
                    O[i][j] += ap[i] * bv[j];
        }
        __syncthreads();   // all smem reads done before next tile's loads
    }

    // normalize + write concat layout
    #pragma unroll
    for (int i = 0; i < 8; i++) {
        float inv = 1.0f / l_[i];
        int q = q0 + tm + 16 * i;
        float* Ob = g_O + ((size_t)(b * TT + q)) * DD + h * DH;
        #pragma unroll
        for (int j = 0; j < 4; j++)
            Ob[tn + 16 * j] = O[i][j] * inv;
    }
}

// ---------------------------------------------------------------------------
// Kernel 3: fusion GEMM  C[4096,1024] = g_O @ Wf + bf
// 128x128 tile, BK=32, 8x8 microtile, 256 threads.
// ---------------------------------------------------------------------------
__global__ __launch_bounds__(256, 2) void fuse_kernel(
    const float* __restrict__ Wf, const float* __restrict__ bf,
    float* __restrict__ C)
{
    __shared__ float sA[32 * 129];   // [k][m] transposed, pad 129
    __shared__ float sB[32 * 128];   // [k][n]

    int tid = threadIdx.x;
    int tn = tid & 15;
    int tm = tid >> 4;
    int m0 = blockIdx.y * 128;
    int n0 = blockIdx.x * 128;
    const float* A = g_O;

    float acc[8][8];
    #pragma unroll
    for (int i = 0; i < 8; i++)
        #pragma unroll
        for (int j = 0; j < 8; j++) acc[i][j] = 0.0f;

    for (int k0 = 0; k0 < 1024; k0 += 32) {
        // A tile transpose: sA[k][m]
        for (int i = tid; i < 1024; i += 256) {
            int mm = i >> 3, kq = (i & 7) * 4;
            float4 v = *reinterpret_cast<const float4*>(
                A + (size_t)(m0 + mm) * 1024 + k0 + kq);
            sA[(kq + 0) * 129 + mm] = v.x;
            sA[(kq + 1) * 129 + mm] = v.y;
            sA[(kq + 2) * 129 + mm] = v.z;
            sA[(kq + 3) * 129 + mm] = v.w;
        }
        // B tile direct
        for (int i = tid; i < 1024; i += 256) {
            int kk = i >> 5, n4 = (i & 31) * 4;
            *reinterpret_cast<float4*>(&sB[kk * 128 + n4]) =
                *reinterpret_cast<const float4*>(Wf + (size_t)(k0 + kk) * 1024 + n0 + n4);
        }
        __syncthreads();

        #pragma unroll 8
        for (int kk = 0; kk < 32; kk++) {
            float a[8], bb[8];
            #pragma unroll
            for (int i = 0; i < 8; i++) a[i]  = sA[kk * 129 + tm + 16 * i];
            #pragma unroll
            for (int j = 0; j < 8; j++) bb[j] = sB[kk * 128 + tn + 16 * j];
            #pragma unroll
            for (int i = 0; i < 8; i++)
                #pragma unroll
                for (int j = 0; j < 8; j++)
                    acc[i][j] += a[i] * bb[j];
        }
        __syncthreads();
    }

    #pragma unroll
    for (int i = 0; i < 8; i++) {
        int m = m0 + tm + 16 * i;
        #pragma unroll
        for (int j = 0; j < 8; j++) {
            int n = n0 + tn + 16 * j;
            C[(size_t)m * 1024 + n] = acc[i][j] + bf[n];
        }
    }
}

// ---------------------------------------------------------------------------
extern "C" void kernel_launch(void* const* d_in, const int* in_sizes, int n_in,
                              void* d_out, int out_size)
{
    const float* X    = (const float*)d_in[0];
    const int*   mask = (const int*)  d_in[1];
    const float* Wq   = (const float*)d_in[2];
    const float* bq   = (const float*)d_in[3];
    const float* Wk   = (const float*)d_in[4];
    const float* bk   = (const float*)d_in[5];
    const float* Wv   = (const float*)d_in[6];
    const float* bv   = (const float*)d_in[7];
    const float* Wf   = (const float*)d_in[8];
    const float* bf   = (const float*)d_in[9];
    float* out = (float*)d_out;

    cudaFuncSetAttribute(attn_kernel,
                         cudaFuncAttributeMaxDynamicSharedMemorySize, ATTN_SMEM);

    dim3 grid1(TT / 64, BB * HH);
    qkv_kernel<<<grid1, 256>>>(X, Wq, bq, Wk, bk, Wv, bv);

    dim3 grid2(TT / 128, BB * HH);
    attn_kernel<<<grid2, 256, ATTN_SMEM>>>(mask);

    dim3 grid3(1024 / 128, (BB * TT) / 128);
    fuse_kernel<<<grid3, 256>>>(Wf, bf, out);
}

// round 5
// speedup vs baseline: 4.4896x; 1.2855x over previous
#include <cuda_runtime.h>
#include <cuda_bf16.h>
#include <cstdint>

#define BB 8
#define TT 512
#define DD 1024
#define HH 16
#define DH 64

// Intermediates (device globals; no allocs allowed).
// Q/K/V stored TRANSPOSED per head: [bh][d(64)][t(512)]
__device__ float g_Q[BB * HH * DH * TT];
__device__ float g_K[BB * HH * DH * TT];
__device__ float g_V[BB * HH * DH * TT];
// attention output, concat layout [B*T][D]
__device__ float g_O[BB * TT * DD];
// bf16 hi/lo splits for the fusion GEMM
__device__ unsigned short g_Ah[BB * TT * DD];   // [m][k]
__device__ unsigned short g_Al[BB * TT * DD];
__device__ unsigned short g_Wh[DD * DD];        // W^T: [n][k]
__device__ unsigned short g_Wl[DD * DD];

// ---------------------------------------------------------------------------
// Kernel 1: QKV projections (unchanged)
// ---------------------------------------------------------------------------
__global__ __launch_bounds__(256) void qkv_kernel(
    const float* __restrict__ X,
    const float* __restrict__ Wq, const float* __restrict__ bq,
    const float* __restrict__ Wk, const float* __restrict__ bk,
    const float* __restrict__ Wv, const float* __restrict__ bv)
{
    __shared__ float Xs[64 * 65];
    __shared__ float Ws[64 * 64];

    int bh = blockIdx.y;
    int b  = bh >> 4;
    int h  = bh & 15;
    int t0 = blockIdx.x * 64;
    int tid = threadIdx.x;
    int tn = tid & 15;
    int tm = tid >> 4;

    const float* Xb = X + ((size_t)(b * TT + t0)) * DD + h * DH;
    for (int i = tid; i < 1024; i += 256) {
        int t = i >> 4, d4 = (i & 15) * 4;
        float4 v = *reinterpret_cast<const float4*>(Xb + (size_t)t * DD + d4);
        Xs[(d4 + 0) * 65 + t] = v.x;
        Xs[(d4 + 1) * 65 + t] = v.y;
        Xs[(d4 + 2) * 65 + t] = v.z;
        Xs[(d4 + 3) * 65 + t] = v.w;
    }

    const float* Wl[3] = {Wq, Wk, Wv};
    const float* bl[3] = {bq, bk, bv};
    float* Ol[3];
    Ol[0] = g_Q; Ol[1] = g_K; Ol[2] = g_V;

    for (int p = 0; p < 3; p++) {
        __syncthreads();
        const float* W = Wl[p] + h * DH * DH;
        for (int i = tid; i < 1024; i += 256) {
            int d = i >> 4, e4 = (i & 15) * 4;
            *reinterpret_cast<float4*>(&Ws[d * 64 + e4]) =
                *reinterpret_cast<const float4*>(W + d * 64 + e4);
        }
        __syncthreads();

        float acc[4][4];
        #pragma unroll
        for (int j = 0; j < 4; j++)
            #pragma unroll
            for (int i = 0; i < 4; i++) acc[j][i] = 0.0f;

        #pragma unroll 8
        for (int d = 0; d < 64; d++) {
            float a[4], bb[4];
            #pragma unroll
            for (int j = 0; j < 4; j++) a[j] = Ws[d * 64 + tm * 4 + j];
            #pragma unroll
            for (int i = 0; i < 4; i++) bb[i] = Xs[d * 65 + tn + 16 * i];
            #pragma unroll
            for (int j = 0; j < 4; j++)
                #pragma unroll
                for (int i = 0; i < 4; i++)
                    acc[j][i] += a[j] * bb[i];
        }

        const float* bias = bl[p] + h * DH;
        float* O = Ol[p] + (size_t)bh * DH * TT;
        #pragma unroll
        for (int j = 0; j < 4; j++) {
            int e = tm * 4 + j;
            float be = bias[e];
            #pragma unroll
            for (int i = 0; i < 4; i++)
                O[(size_t)e * TT + t0 + tn + 16 * i] = acc[j][i] + be;
        }
    }
}

// ---------------------------------------------------------------------------
// Kernel 2: flash attention (unchanged)
// ---------------------------------------------------------------------------
#define QS_OFF 0
#define KS_OFF (QS_OFF + 64 * 128)
#define VS_OFF (KS_OFF + 64 * 64)
#define PS_OFF (VS_OFF + 64 * 65)
#define MS_OFF (PS_OFF + 64 * 129)
#define ATTN_SMEM ((MS_OFF + 512) * 4)

__global__ __launch_bounds__(256, 2) void attn_kernel(const int* __restrict__ mask)
{
    extern __shared__ float sm[];
    float* sQ = sm + QS_OFF;
    float* sK = sm + KS_OFF;
    float* sV = sm + VS_OFF;
    float* sP = sm + PS_OFF;
    int*   sM = (int*)(sm + MS_OFF);

    int bh = blockIdx.y;
    int b  = bh >> 4;
    int h  = bh & 15;
    int q0 = blockIdx.x * 128;
    int tid = threadIdx.x;
    int tn = tid & 15;
    int tm = tid >> 4;

    const float* Qg = g_Q + (size_t)bh * DH * TT;
    const float* Kg = g_K + (size_t)bh * DH * TT;
    const float* Vg = g_V + (size_t)bh * DH * TT;

    for (int i = tid; i < 2048; i += 256) {
        int d = i >> 5, q4 = (i & 31) * 4;
        *reinterpret_cast<float4*>(&sQ[d * 128 + q4]) =
            *reinterpret_cast<const float4*>(Qg + (size_t)d * TT + q0 + q4);
    }
    for (int i = tid; i < TT; i += 256) sM[i] = mask[b * TT + i];
    __syncthreads();

    float m_[8], l_[8], O[8][4];
    #pragma unroll
    for (int i = 0; i < 8; i++) {
        m_[i] = -1e30f; l_[i] = 0.0f;
        #pragma unroll
        for (int j = 0; j < 4; j++) O[i][j] = 0.0f;
    }

    for (int kt = 0; kt < TT; kt += 64) {
        for (int i = tid; i < 1024; i += 256) {
            int d = i >> 4, k4 = (i & 15) * 4;
            *reinterpret_cast<float4*>(&sK[d * 64 + k4]) =
                *reinterpret_cast<const float4*>(Kg + (size_t)d * TT + kt + k4);
        }
        for (int i = tid; i < 1024; i += 256) {
            int d = i >> 4, k4 = (i & 15) * 4;
            float4 v = *reinterpret_cast<const float4*>(Vg + (size_t)d * TT + kt + k4);
            sV[(k4 + 0) * 65 + d] = v.x;
            sV[(k4 + 1) * 65 + d] = v.y;
            sV[(k4 + 2) * 65 + d] = v.z;
            sV[(k4 + 3) * 65 + d] = v.w;
        }
        __syncthreads();

        float S[8][4];
        #pragma unroll
        for (int i = 0; i < 8; i++)
            #pragma unroll
            for (int j = 0; j < 4; j++) S[i][j] = 0.0f;

        #pragma unroll 4
        for (int d = 0; d < 64; d++) {
            float a[8], bb[4];
            #pragma unroll
            for (int i = 0; i < 8; i++) a[i] = sQ[d * 128 + tm + 16 * i];
            #pragma unroll
            for (int j = 0; j < 4; j++) bb[j] = sK[d * 64 + tn + 16 * j];
            #pragma unroll
            for (int i = 0; i < 8; i++)
                #pragma unroll
                for (int j = 0; j < 4; j++)
                    S[i][j] += a[i] * bb[j];
        }

        int mk[4];
        #pragma unroll
        for (int j = 0; j < 4; j++) mk[j] = sM[kt + tn + 16 * j];
        #pragma unroll
        for (int i = 0; i < 8; i++)
            #pragma unroll
            for (int j = 0; j < 4; j++)
                S[i][j] = (mk[j] > 0) ? S[i][j] * 0.125f : -1e9f;

        #pragma unroll
        for (int i = 0; i < 8; i++) {
            float mx = S[i][0];
            #pragma unroll
            for (int j = 1; j < 4; j++) mx = fmaxf(mx, S[i][j]);
            mx = fmaxf(mx, __shfl_xor_sync(0xffffffffu, mx, 1, 16));
            mx = fmaxf(mx, __shfl_xor_sync(0xffffffffu, mx, 2, 16));
            mx = fmaxf(mx, __shfl_xor_sync(0xffffffffu, mx, 4, 16));
            mx = fmaxf(mx, __shfl_xor_sync(0xffffffffu, mx, 8, 16));
            float mnew  = fmaxf(m_[i], mx);
            float alpha = __expf(m_[i] - mnew);
            float rs = 0.0f;
            #pragma unroll
            for (int j = 0; j < 4; j++) {
                S[i][j] = __expf(S[i][j] - mnew);
                rs += S[i][j];
            }
            rs += __shfl_xor_sync(0xffffffffu, rs, 1, 16);
            rs += __shfl_xor_sync(0xffffffffu, rs, 2, 16);
            rs += __shfl_xor_sync(0xffffffffu, rs, 4, 16);
            rs += __shfl_xor_sync(0xffffffffu, rs, 8, 16);
            l_[i] = l_[i] * alpha + rs;
            m_[i] = mnew;
            #pragma unroll
            for (int j = 0; j < 4; j++) O[i][j] *= alpha;
        }

        #pragma unroll
        for (int i = 0; i < 8; i++)
            #pragma unroll
            for (int j = 0; j < 4; j++)
                sP[(tn + 16 * j) * 129 + tm + 16 * i] = S[i][j];
        __syncthreads();

        #pragma unroll 4
        for (int kk = 0; kk < 64; kk++) {
            float ap[8], bv[4];
            #pragma unroll
            for (int i = 0; i < 8; i++) ap[i] = sP[kk * 129 + tm + 16 * i];
            #pragma unroll
            for (int j = 0; j < 4; j++) bv[j] = sV[kk * 65 + tn + 16 * j];
            #pragma unroll
            for (int i = 0; i < 8; i++)
                #pragma unroll
                for (int j = 0; j < 4; j++)
                    O[i][j] += ap[i] * bv[j];
        }
        __syncthreads();
    }

    #pragma unroll
    for (int i = 0; i < 8; i++) {
        float inv = 1.0f / l_[i];
        int q = q0 + tm + 16 * i;
        float* Ob = g_O + ((size_t)(b * TT + q)) * DD + h * DH;
        #pragma unroll
        for (int j = 0; j < 4; j++)
            Ob[tn + 16 * j] = O[i][j] * inv;
    }
}

// ---------------------------------------------------------------------------
// Kernel 3a: split g_O (fp32) -> g_Ah/g_Al (bf16 hi/lo), same layout
// ---------------------------------------------------------------------------
__global__ __launch_bounds__(256) void convA_kernel()
{
    int i = (blockIdx.x * 256 + threadIdx.x) * 4;
    float4 v = *reinterpret_cast<const float4*>(g_O + i);
    uint32_t bx = __float_as_uint(v.x), by = __float_as_uint(v.y);
    uint32_t bz = __float_as_uint(v.z), bw = __float_as_uint(v.w);
    uint32_t h01 = __byte_perm(bx, by, 0x7632);
    uint32_t h23 = __byte_perm(bz, bw, 0x7632);
    float l0 = v.x - __uint_as_float(bx & 0xFFFF0000u);
    float l1 = v.y - __uint_as_float(by & 0xFFFF0000u);
    float l2 = v.z - __uint_as_float(bz & 0xFFFF0000u);
    float l3 = v.w - __uint_as_float(bw & 0xFFFF0000u);
    uint32_t p01, p23;
    asm("cvt.rn.bf16x2.f32 %0, %1, %2;" : "=r"(p01) : "f"(l1), "f"(l0));
    asm("cvt.rn.bf16x2.f32 %0, %1, %2;" : "=r"(p23) : "f"(l3), "f"(l2));
    uint2 hv = make_uint2(h01, h23), lv = make_uint2(p01, p23);
    *reinterpret_cast<uint2*>(g_Ah + i) = hv;
    *reinterpret_cast<uint2*>(g_Al + i) = lv;
}

// ---------------------------------------------------------------------------
// Kernel 3b: Wf [k][n] fp32 -> g_Wh/g_Wl [n][k] bf16 (transpose + split)
// ---------------------------------------------------------------------------
__global__ __launch_bounds__(256) void convW_kernel(const float* __restrict__ Wf)
{
    __shared__ float t[32][33];
    int k0 = blockIdx.x * 32, n0 = blockIdx.y * 32;
    int tx = threadIdx.x & 31, ty = threadIdx.x >> 5;
    #pragma unroll
    for (int j = 0; j < 4; j++)
        t[ty + 8 * j][tx] = Wf[(size_t)(k0 + ty + 8 * j) * DD + n0 + tx];
    __syncthreads();
    #pragma unroll
    for (int j = 0; j < 4; j++) {
        int k = k0 + tx, n = n0 + ty + 8 * j;
        float v = t[tx][ty + 8 * j];
        uint32_t bi = __float_as_uint(v);
        float lo = v - __uint_as_float(bi & 0xFFFF0000u);
        uint32_t p;
        asm("cvt.rn.bf16x2.f32 %0, %1, %2;" : "=r"(p) : "f"(lo), "f"(lo));
        g_Wh[(size_t)n * DD + k] = (unsigned short)(bi >> 16);
        g_Wl[(size_t)n * DD + k] = (unsigned short)(p & 0xFFFF);
    }
}

// ---------------------------------------------------------------------------
// Kernel 4: fusion GEMM via mma.sync (bf16 HMMA, fp32 acc)
// C[4096,1024] = A @ W + bf,  D = Ah·Wh + Ah·Wl + Al·Wh
// CTA tile 128m x 64n, BK=64, 8 warps (4m x 2n), warp tile 32m x 32n.
// smem stride 72 bf16 -> conflict-free 32b fragment loads.
// ---------------------------------------------------------------------------
#define FSTR 72
#define SM_AH 0
#define SM_AL (SM_AH + 128 * FSTR)
#define SM_BH (SM_AL + 128 * FSTR)
#define SM_BL (SM_BH + 64 * FSTR)
#define FUSE_SMEM ((SM_BL + 64 * FSTR) * 2)   // bytes

__device__ __forceinline__ void mma16816(float* c, const uint32_t* a, const uint32_t* b) {
    asm volatile(
        "mma.sync.aligned.m16n8k16.row.col.f32.bf16.bf16.f32 "
        "{%0,%1,%2,%3}, {%4,%5,%6,%7}, {%8,%9}, {%0,%1,%2,%3};"
        : "+f"(c[0]), "+f"(c[1]), "+f"(c[2]), "+f"(c[3])
        : "r"(a[0]), "r"(a[1]), "r"(a[2]), "r"(a[3]), "r"(b[0]), "r"(b[1]));
}

__global__ __launch_bounds__(256, 2) void fuse_mma_kernel(
    const float* __restrict__ bf, float* __restrict__ C)
{
    extern __shared__ unsigned short fsm[];
    unsigned short* sAh = fsm + SM_AH;
    unsigned short* sAl = fsm + SM_AL;
    unsigned short* sBh = fsm + SM_BH;
    unsigned short* sBl = fsm + SM_BL;

    int tid = threadIdx.x;
    int wid = tid >> 5;
    int lane = tid & 31;
    int g = lane >> 2;        // 0..7
    int t = lane & 3;         // 0..3
    int wm = wid >> 1;        // 0..3 -> m offset 32*wm
    int wn = wid & 1;         // 0..1 -> n offset 32*wn

    int n0 = blockIdx.x * 64;
    int m0 = blockIdx.y * 128;

    float acc[2][4][4];
    #pragma unroll
    for (int mt = 0; mt < 2; mt++)
        #pragma unroll
        for (int nt = 0; nt < 4; nt++)
            #pragma unroll
            for (int r = 0; r < 4; r++) acc[mt][nt][r] = 0.0f;

    for (int k0 = 0; k0 < DD; k0 += 64) {
        // A tiles: 128 rows x 64 k, 1024 uint4 per matrix
        for (int i = tid; i < 1024; i += 256) {
            int row = i >> 3, c8 = i & 7;
            size_t ga = (size_t)(m0 + row) * DD + k0 + c8 * 8;
            *reinterpret_cast<uint4*>(&sAh[row * FSTR + c8 * 8]) =
                *reinterpret_cast<const uint4*>(g_Ah + ga);
            *reinterpret_cast<uint4*>(&sAl[row * FSTR + c8 * 8]) =
                *reinterpret_cast<const uint4*>(g_Al + ga);
        }
        // B tiles: 64 rows x 64 k, 512 uint4 per matrix
        for (int i = tid; i < 512; i += 256) {
            int row = i >> 3, c8 = i & 7;
            size_t gb = (size_t)(n0 + row) * DD + k0 + c8 * 8;
            *reinterpret_cast<uint4*>(&sBh[row * FSTR + c8 * 8]) =
                *reinterpret_cast<const uint4*>(g_Wh + gb);
            *reinterpret_cast<uint4*>(&sBl[row * FSTR + c8 * 8]) =
                *reinterpret_cast<const uint4*>(g_Wl + gb);
        }
        __syncthreads();

        #pragma unroll
        for (int ks = 0; ks < 4; ks++) {
            int k = ks * 16;
            // A fragments (hi & lo) for 2 m-tiles
            uint32_t ah[2][4], al[2][4];
            #pragma unroll
            for (int mt = 0; mt < 2; mt++) {
                int r0 = (wm * 32 + mt * 16 + g) * FSTR + k + t * 2;
                int r1 = r0 + 8 * FSTR;
                ah[mt][0] = *reinterpret_cast<const uint32_t*>(&sAh[r0]);
                ah[mt][1] = *reinterpret_cast<const uint32_t*>(&sAh[r1]);
                ah[mt][2] = *reinterpret_cast<const uint32_t*>(&sAh[r0 + 8]);
                ah[mt][3] = *reinterpret_cast<const uint32_t*>(&sAh[r1 + 8]);
                al[mt][0] = *reinterpret_cast<const uint32_t*>(&sAl[r0]);
                al[mt][1] = *reinterpret_cast<const uint32_t*>(&sAl[r1]);
                al[mt][2] = *reinterpret_cast<const uint32_t*>(&sAl[r0 + 8]);
                al[mt][3] = *reinterpret_cast<const uint32_t*>(&sAl[r1 + 8]);
            }
            // B fragments (hi & lo) for 4 n-tiles
            uint32_t bh[4][2], blo[4][2];
            #pragma unroll
            for (int nt = 0; nt < 4; nt++) {
                int r0 = (wn * 32 + nt * 8 + g) * FSTR + k + t * 2;
                bh[nt][0]  = *reinterpret_cast<const uint32_t*>(&sBh[r0]);
                bh[nt][1]  = *reinterpret_cast<const uint32_t*>(&sBh[r0 + 8]);
                blo[nt][0] = *reinterpret_cast<const uint32_t*>(&sBl[r0]);
                blo[nt][1] = *reinterpret_cast<const uint32_t*>(&sBl[r0 + 8]);
            }
            #pragma unroll
            for (int mt = 0; mt < 2; mt++)
                #pragma unroll
                for (int nt = 0; nt < 4; nt++) {
                    mma16816(acc[mt][nt], ah[mt], bh[nt]);
                    mma16816(acc[mt][nt], ah[mt], blo[nt]);
                    mma16816(acc[mt][nt], al[mt], bh[nt]);
                }
        }
        __syncthreads();
    }

    // epilogue: C fragment -> global with bias
    #pragma unroll
    for (int nt = 0; nt < 4; nt++) {
        int n = n0 + wn * 32 + nt * 8 + t * 2;
        float b0 = bf[n], b1 = bf[n + 1];
        #pragma unroll
        for (int mt = 0; mt < 2; mt++) {
            int m = m0 + wm * 32 + mt * 16 + g;
            float2 v0 = make_float2(acc[mt][nt][0] + b0, acc[mt][nt][1] + b1);
            float2 v1 = make_float2(acc[mt][nt][2] + b0, acc[mt][nt][3] + b1);
            *reinterpret_cast<float2*>(C + (size_t)m * DD + n) = v0;
            *reinterpret_cast<float2*>(C + (size_t)(m + 8) * DD + n) = v1;
        }
    }
}

// ---------------------------------------------------------------------------
extern "C" void kernel_launch(void* const* d_in, const int* in_sizes, int n_in,
                              void* d_out, int out_size)
{
    const float* X    = (const float*)d_in[0];
    const int*   mask = (const int*)  d_in[1];
    const float* Wq   = (const float*)d_in[2];
    const float* bq   = (const float*)d_in[3];
    const float* Wk   = (const float*)d_in[4];
    const float* bk   = (const float*)d_in[5];
    const float* Wv   = (const float*)d_in[6];
    const float* bv   = (const float*)d_in[7];
    const float* Wf   = (const float*)d_in[8];
    const float* bf   = (const float*)d_in[9];
    float* out = (float*)d_out;

    cudaFuncSetAttribute(attn_kernel,
                         cudaFuncAttributeMaxDynamicSharedMemorySize, ATTN_SMEM);
    cudaFuncSetAttribute(fuse_mma_kernel,
                         cudaFuncAttributeMaxDynamicSharedMemorySize, FUSE_SMEM);

    dim3 grid1(TT / 64, BB * HH);
    qkv_kernel<<<grid1, 256>>>(X, Wq, bq, Wk, bk, Wv, bv);

    convW_kernel<<<dim3(32, 32), 256>>>(Wf);

    dim3 grid2(TT / 128, BB * HH);
    attn_kernel<<<grid2, 256, ATTN_SMEM>>>(mask);

    convA_kernel<<<(BB * TT * DD) / 1024, 256>>>();

    dim3 grid4(DD / 64, (BB * TT) / 128);
    fuse_mma_kernel<<<grid4, 256, FUSE_SMEM>>>(bf, out);
}

// round 6
// speedup vs baseline: 7.0975x; 1.5809x over previous
#include <cuda_runtime.h>
#include <cuda_bf16.h>
#include <cstdint>

#define BB 8
#define TT 512
#define DD 1024
#define HH 16
#define DH 64

// bf16 hi/lo splits (device globals; no allocs allowed)
__device__ unsigned short g_Qh[BB * HH * TT * DH];   // [bh][t][d]  (Q pre-scaled by 1/8)
__device__ unsigned short g_Ql[BB * HH * TT * DH];
__device__ unsigned short g_Kh[BB * HH * TT * DH];   // [bh][t][d]
__device__ unsigned short g_Kl[BB * HH * TT * DH];
__device__ unsigned short g_Vh[BB * HH * DH * TT];   // [bh][d][t]
__device__ unsigned short g_Vl[BB * HH * DH * TT];
__device__ unsigned short g_Ah[BB * TT * DD];        // attention out split [m][k]
__device__ unsigned short g_Al[BB * TT * DD];
__device__ unsigned short g_Wh[DD * DD];             // W^T: [n][k]
__device__ unsigned short g_Wl[DD * DD];

__device__ __forceinline__ void mma16816(float* c, const uint32_t* a, const uint32_t* b) {
    asm volatile(
        "mma.sync.aligned.m16n8k16.row.col.f32.bf16.bf16.f32 "
        "{%0,%1,%2,%3}, {%4,%5,%6,%7}, {%8,%9}, {%0,%1,%2,%3};"
        : "+f"(c[0]), "+f"(c[1]), "+f"(c[2]), "+f"(c[3])
        : "r"(a[0]), "r"(a[1]), "r"(a[2]), "r"(a[3]), "r"(b[0]), "r"(b[1]));
}

__device__ __forceinline__ void fsplit(float v, unsigned short& h, unsigned short& l) {
    uint32_t b = __float_as_uint(v);
    h = (unsigned short)(b >> 16);
    float lo = v - __uint_as_float(b & 0xFFFF0000u);
    uint32_t p;
    asm("cvt.rn.bf16x2.f32 %0, %1, %2;" : "=r"(p) : "f"(lo), "f"(lo));
    l = (unsigned short)(p & 0xFFFF);
}

// ---------------------------------------------------------------------------
// Kernel 1: QKV projections -> bf16 hi/lo splits in MMA layouts.
// grid (T/64, B*H), 256 threads. Q pre-scaled by 0.125.
// ---------------------------------------------------------------------------
__global__ __launch_bounds__(256) void qkv_kernel(
    const float* __restrict__ X,
    const float* __restrict__ Wq, const float* __restrict__ bq,
    const float* __restrict__ Wk, const float* __restrict__ bk,
    const float* __restrict__ Wv, const float* __restrict__ bv)
{
    __shared__ float Xs[64 * 65];
    __shared__ float Ws[64 * 64];   // reused as ushort staging after compute

    int bh = blockIdx.y;
    int b  = bh >> 4;
    int h  = bh & 15;
    int t0 = blockIdx.x * 64;
    int tid = threadIdx.x;
    int tn = tid & 15;
    int tm = tid >> 4;

    const float* Xb = X + ((size_t)(b * TT + t0)) * DD + h * DH;
    for (int i = tid; i < 1024; i += 256) {
        int t = i >> 4, d4 = (i & 15) * 4;
        float4 v = *reinterpret_cast<const float4*>(Xb + (size_t)t * DD + d4);
        Xs[(d4 + 0) * 65 + t] = v.x;
        Xs[(d4 + 1) * 65 + t] = v.y;
        Xs[(d4 + 2) * 65 + t] = v.z;
        Xs[(d4 + 3) * 65 + t] = v.w;
    }

    const float* Wl[3] = {Wq, Wk, Wv};
    const float* bl[3] = {bq, bk, bv};

    for (int p = 0; p < 3; p++) {
        __syncthreads();
        const float* W = Wl[p] + h * DH * DH;
        for (int i = tid; i < 1024; i += 256) {
            int d = i >> 4, e4 = (i & 15) * 4;
            *reinterpret_cast<float4*>(&Ws[d * 64 + e4]) =
                *reinterpret_cast<const float4*>(W + d * 64 + e4);
        }
        __syncthreads();

        float acc[4][4];
        #pragma unroll
        for (int j = 0; j < 4; j++)
            #pragma unroll
            for (int i = 0; i < 4; i++) acc[j][i] = 0.0f;

        #pragma unroll 8
        for (int d = 0; d < 64; d++) {
            float a[4], bb[4];
            #pragma unroll
            for (int j = 0; j < 4; j++) a[j] = Ws[d * 64 + tm * 4 + j];
            #pragma unroll
            for (int i = 0; i < 4; i++) bb[i] = Xs[d * 65 + tn + 16 * i];
            #pragma unroll
            for (int j = 0; j < 4; j++)
                #pragma unroll
                for (int i = 0; i < 4; i++)
                    acc[j][i] += a[j] * bb[i];
        }

        const float* bias = bl[p] + h * DH;
        float qscale = (p == 0) ? 0.125f : 1.0f;

        __syncthreads();   // everyone done reading Ws -> reuse as staging
        unsigned short* sH = reinterpret_cast<unsigned short*>(Ws);
        unsigned short* sL = sH + 4096;

        #pragma unroll
        for (int j = 0; j < 4; j++) {
            int e = tm * 4 + j;
            float be = bias[e];
            #pragma unroll
            for (int i = 0; i < 4; i++) {
                int t = tn + 16 * i;
                float v = (acc[j][i] + be) * qscale;
                unsigned short hh, ll;
                fsplit(v, hh, ll);
                int idx = (p < 2) ? (t * 64 + e) : (e * 64 + t);
                sH[idx] = hh;
                sL[idx] = ll;
            }
        }
        __syncthreads();

        unsigned short* Hd;
        unsigned short* Ld;
        if (p == 0)      { Hd = g_Qh; Ld = g_Ql; }
        else if (p == 1) { Hd = g_Kh; Ld = g_Kl; }
        else             { Hd = g_Vh; Ld = g_Vl; }

        for (int i = tid; i < 512; i += 256) {
            int row = i >> 3, c8 = (i & 7) * 8;
            uint4 vh = reinterpret_cast<const uint4*>(sH)[i];
            uint4 vl = reinterpret_cast<const uint4*>(sL)[i];
            size_t off;
            if (p < 2) off = ((size_t)bh * TT + t0 + row) * DH + c8;       // [t][d]
            else       off = ((size_t)bh * DH + row) * TT + t0 + c8;       // [d][t]
            *reinterpret_cast<uint4*>(Hd + off) = vh;
            *reinterpret_cast<uint4*>(Ld + off) = vl;
        }
    }
}

// ---------------------------------------------------------------------------
// Kernel 2: flash attention via mma.sync bf16-split.
// grid (T/128, B*H), 128 threads (4 warps), warp = 32q x 64 keys.
// ---------------------------------------------------------------------------
#define ASTR 72
#define A_QH 0
#define A_QL (A_QH + 128 * ASTR)
#define A_KH (A_QL + 128 * ASTR)
#define A_KL (A_KH + 64 * ASTR)
#define A_VH (A_KL + 64 * ASTR)
#define A_VL (A_VH + 64 * ASTR)
#define A_MSK (A_VL + 64 * ASTR)           // 512 ints = 1024 ushorts
#define ATTN_SMEM ((A_MSK + 1024) * 2)

__global__ __launch_bounds__(128) void attn_mma_kernel(const int* __restrict__ mask)
{
    extern __shared__ unsigned short shm[];
    unsigned short* sQh = shm + A_QH;
    unsigned short* sQl = shm + A_QL;
    unsigned short* sKh = shm + A_KH;
    unsigned short* sKl = shm + A_KL;
    unsigned short* sVh = shm + A_VH;
    unsigned short* sVl = shm + A_VL;
    int* sMask = (int*)(shm + A_MSK);

    int tid = threadIdx.x;
    int wid = tid >> 5;
    int lane = tid & 31;
    int g = lane >> 2;
    int t = lane & 3;
    int wq = wid * 32;

    int bh = blockIdx.y;
    int b  = bh >> 4;
    int h  = bh & 15;
    int q0 = blockIdx.x * 128;

    // load Q tiles (128 x 64, hi/lo)
    {
        const unsigned short* Qhg = g_Qh + ((size_t)bh * TT + q0) * DH;
        const unsigned short* Qlg = g_Ql + ((size_t)bh * TT + q0) * DH;
        for (int i = tid; i < 1024; i += 128) {
            int row = i >> 3, c8 = (i & 7) * 8;
            *reinterpret_cast<uint4*>(&sQh[row * ASTR + c8]) =
                *reinterpret_cast<const uint4*>(Qhg + row * DH + c8);
            *reinterpret_cast<uint4*>(&sQl[row * ASTR + c8]) =
                *reinterpret_cast<const uint4*>(Qlg + row * DH + c8);
        }
        for (int i = tid; i < TT; i += 128) sMask[i] = mask[b * TT + i];
    }
    __syncthreads();

    float O[2][8][4];
    float m_[2][2], l_[2][2];
    #pragma unroll
    for (int mt = 0; mt < 2; mt++) {
        m_[mt][0] = m_[mt][1] = -1e30f;
        l_[mt][0] = l_[mt][1] = 0.0f;
        #pragma unroll
        for (int nt = 0; nt < 8; nt++)
            #pragma unroll
            for (int r = 0; r < 4; r++) O[mt][nt][r] = 0.0f;
    }

    for (int kt = 0; kt < 8; kt++) {
        int kb = kt * 64;
        // load K (64x64 [key][d]) and V (64x64 [d][key]) hi/lo
        for (int i = tid; i < 512; i += 128) {
            int row = i >> 3, c8 = (i & 7) * 8;
            size_t ko = ((size_t)bh * TT + kb + row) * DH + c8;
            size_t vo = ((size_t)bh * DH + row) * TT + kb + c8;
            *reinterpret_cast<uint4*>(&sKh[row * ASTR + c8]) =
                *reinterpret_cast<const uint4*>(g_Kh + ko);
            *reinterpret_cast<uint4*>(&sKl[row * ASTR + c8]) =
                *reinterpret_cast<const uint4*>(g_Kl + ko);
            *reinterpret_cast<uint4*>(&sVh[row * ASTR + c8]) =
                *reinterpret_cast<const uint4*>(g_Vh + vo);
            *reinterpret_cast<uint4*>(&sVl[row * ASTR + c8]) =
                *reinterpret_cast<const uint4*>(g_Vl + vo);
        }
        __syncthreads();

        // ---- S = Q K^T (3-term split) ----
        float S[2][8][4];
        #pragma unroll
        for (int mt = 0; mt < 2; mt++)
            #pragma unroll
            for (int nt = 0; nt < 8; nt++)
                #pragma unroll
                for (int r = 0; r < 4; r++) S[mt][nt][r] = 0.0f;

        #pragma unroll
        for (int ks = 0; ks < 4; ks++) {
            uint32_t qh[2][4], ql[2][4];
            #pragma unroll
            for (int mt = 0; mt < 2; mt++) {
                int base = (wq + mt * 16 + g) * ASTR + ks * 16 + t * 2;
                qh[mt][0] = *reinterpret_cast<const uint32_t*>(&sQh[base]);
                qh[mt][1] = *reinterpret_cast<const uint32_t*>(&sQh[base + 8 * ASTR]);
                qh[mt][2] = *reinterpret_cast<const uint32_t*>(&sQh[base + 8]);
                qh[mt][3] = *reinterpret_cast<const uint32_t*>(&sQh[base + 8 * ASTR + 8]);
                ql[mt][0] = *reinterpret_cast<const uint32_t*>(&sQl[base]);
                ql[mt][1] = *reinterpret_cast<const uint32_t*>(&sQl[base + 8 * ASTR]);
                ql[mt][2] = *reinterpret_cast<const uint32_t*>(&sQl[base + 8]);
                ql[mt][3] = *reinterpret_cast<const uint32_t*>(&sQl[base + 8 * ASTR + 8]);
            }
            uint32_t kh[8][2], kl[8][2];
            #pragma unroll
            for (int nt = 0; nt < 8; nt++) {
                int kb2 = (nt * 8 + g) * ASTR + ks * 16 + t * 2;
                kh[nt][0] = *reinterpret_cast<const uint32_t*>(&sKh[kb2]);
                kh[nt][1] = *reinterpret_cast<const uint32_t*>(&sKh[kb2 + 8]);
                kl[nt][0] = *reinterpret_cast<const uint32_t*>(&sKl[kb2]);
                kl[nt][1] = *reinterpret_cast<const uint32_t*>(&sKl[kb2 + 8]);
            }
            #pragma unroll
            for (int mt = 0; mt < 2; mt++)
                #pragma unroll
                for (int nt = 0; nt < 8; nt++) {
                    mma16816(S[mt][nt], qh[mt], kh[nt]);
                    mma16816(S[mt][nt], qh[mt], kl[nt]);
                    mma16816(S[mt][nt], ql[mt], kh[nt]);
                }
        }

        // ---- mask + online softmax (in fragments) ----
        int mk0[8], mk1[8];
        #pragma unroll
        for (int nt = 0; nt < 8; nt++) {
            mk0[nt] = sMask[kb + nt * 8 + 2 * t];
            mk1[nt] = sMask[kb + nt * 8 + 2 * t + 1];
        }
        #pragma unroll
        for (int mt = 0; mt < 2; mt++) {
            #pragma unroll
            for (int nt = 0; nt < 8; nt++) {
                if (mk0[nt] <= 0) { S[mt][nt][0] = -1e9f; S[mt][nt][2] = -1e9f; }
                if (mk1[nt] <= 0) { S[mt][nt][1] = -1e9f; S[mt][nt][3] = -1e9f; }
            }
            #pragma unroll
            for (int r = 0; r < 2; r++) {
                float mx = -1e30f;
                #pragma unroll
                for (int nt = 0; nt < 8; nt++) {
                    mx = fmaxf(mx, S[mt][nt][2 * r]);
                    mx = fmaxf(mx, S[mt][nt][2 * r + 1]);
                }
                mx = fmaxf(mx, __shfl_xor_sync(0xffffffffu, mx, 1));
                mx = fmaxf(mx, __shfl_xor_sync(0xffffffffu, mx, 2));
                float mnew  = fmaxf(m_[mt][r], mx);
                float alpha = __expf(m_[mt][r] - mnew);
                float rs = 0.0f;
                #pragma unroll
                for (int nt = 0; nt < 8; nt++) {
                    float e0 = __expf(S[mt][nt][2 * r]     - mnew);
                    float e1 = __expf(S[mt][nt][2 * r + 1] - mnew);
                    S[mt][nt][2 * r]     = e0;
                    S[mt][nt][2 * r + 1] = e1;
                    rs += e0 + e1;
                }
                rs += __shfl_xor_sync(0xffffffffu, rs, 1);
                rs += __shfl_xor_sync(0xffffffffu, rs, 2);
                l_[mt][r] = l_[mt][r] * alpha + rs;
                m_[mt][r] = mnew;
                #pragma unroll
                for (int nt = 0; nt < 8; nt++) {
                    O[mt][nt][2 * r]     *= alpha;
                    O[mt][nt][2 * r + 1] *= alpha;
                }
            }
        }

        // ---- O += P V (3-term split), P from S fragments ----
        #pragma unroll
        for (int ks = 0; ks < 4; ks++) {
            uint32_t ph[2][4], pl[2][4];
            #pragma unroll
            for (int mt = 0; mt < 2; mt++) {
                #pragma unroll
                for (int half = 0; half < 2; half++) {
                    const float* sv = S[mt][2 * ks + half];
                    uint32_t b0 = __float_as_uint(sv[0]);
                    uint32_t b1 = __float_as_uint(sv[1]);
                    uint32_t b2 = __float_as_uint(sv[2]);
                    uint32_t b3 = __float_as_uint(sv[3]);
                    ph[mt][2 * half]     = __byte_perm(b0, b1, 0x7632);
                    ph[mt][2 * half + 1] = __byte_perm(b2, b3, 0x7632);
                    float l0 = sv[0] - __uint_as_float(b0 & 0xFFFF0000u);
                    float l1 = sv[1] - __uint_as_float(b1 & 0xFFFF0000u);
                    float l2 = sv[2] - __uint_as_float(b2 & 0xFFFF0000u);
                    float l3 = sv[3] - __uint_as_float(b3 & 0xFFFF0000u);
                    asm("cvt.rn.bf16x2.f32 %0, %1, %2;"
                        : "=r"(pl[mt][2 * half]) : "f"(l1), "f"(l0));
                    asm("cvt.rn.bf16x2.f32 %0, %1, %2;"
                        : "=r"(pl[mt][2 * half + 1]) : "f"(l3), "f"(l2));
                }
            }
            uint32_t vh[8][2], vl[8][2];
            #pragma unroll
            for (int nt = 0; nt < 8; nt++) {
                int vo = (nt * 8 + g) * ASTR + ks * 16 + t * 2;
                vh[nt][0] = *reinterpret_cast<const uint32_t*>(&sVh[vo]);
                vh[nt][1] = *reinterpret_cast<const uint32_t*>(&sVh[vo + 8]);
                vl[nt][0] = *reinterpret_cast<const uint32_t*>(&sVl[vo]);
                vl[nt][1] = *reinterpret_cast<const uint32_t*>(&sVl[vo + 8]);
            }
            #pragma unroll
            for (int mt = 0; mt < 2; mt++)
                #pragma unroll
                for (int nt = 0; nt < 8; nt++) {
                    mma16816(O[mt][nt], ph[mt], vh[nt]);
                    mma16816(O[mt][nt], ph[mt], vl[nt]);
                    mma16816(O[mt][nt], pl[mt], vh[nt]);
                }
        }
        __syncthreads();
    }

    // epilogue: normalize, split to bf16 hi/lo, write g_Ah/g_Al [m][1024]
    #pragma unroll
    for (int mt = 0; mt < 2; mt++) {
        #pragma unroll
        for (int r = 0; r < 2; r++) {
            float inv = 1.0f / l_[mt][r];
            int mrow = b * TT + q0 + wq + mt * 16 + g + 8 * r;
            size_t base = (size_t)mrow * DD + h * DH;
            #pragma unroll
            for (int nt = 0; nt < 8; nt++) {
                float v0 = O[mt][nt][2 * r]     * inv;
                float v1 = O[mt][nt][2 * r + 1] * inv;
                uint32_t b0 = __float_as_uint(v0), b1 = __float_as_uint(v1);
                uint32_t hp = __byte_perm(b0, b1, 0x7632);
                float l0 = v0 - __uint_as_float(b0 & 0xFFFF0000u);
                float l1 = v1 - __uint_as_float(b1 & 0xFFFF0000u);
                uint32_t lp;
                asm("cvt.rn.bf16x2.f32 %0, %1, %2;" : "=r"(lp) : "f"(l1), "f"(l0));
                *reinterpret_cast<uint32_t*>(g_Ah + base + nt * 8 + 2 * t) = hp;
                *reinterpret_cast<uint32_t*>(g_Al + base + nt * 8 + 2 * t) = lp;
            }
        }
    }
}

// ---------------------------------------------------------------------------
// Kernel 3: Wf [k][n] fp32 -> g_Wh/g_Wl [n][k] bf16 (transpose + split)
// ---------------------------------------------------------------------------
__global__ __launch_bounds__(256) void convW_kernel(const float* __restrict__ Wf)
{
    __shared__ float t[32][33];
    int k0 = blockIdx.x * 32, n0 = blockIdx.y * 32;
    int tx = threadIdx.x & 31, ty = threadIdx.x >> 5;
    #pragma unroll
    for (int j = 0; j < 4; j++)
        t[ty + 8 * j][tx] = Wf[(size_t)(k0 + ty + 8 * j) * DD + n0 + tx];
    __syncthreads();
    #pragma unroll
    for (int j = 0; j < 4; j++) {
        int k = k0 + tx, n = n0 + ty + 8 * j;
        float v = t[tx][ty + 8 * j];
        unsigned short hh, ll;
        fsplit(v, hh, ll);
        g_Wh[(size_t)n * DD + k] = hh;
        g_Wl[(size_t)n * DD + k] = ll;
    }
}

// ---------------------------------------------------------------------------
// Kernel 4: fusion GEMM via mma.sync (unchanged from R5)
// ---------------------------------------------------------------------------
#define FSTR 72
#define SM_AH 0
#define SM_AL (SM_AH + 128 * FSTR)
#define SM_BH (SM_AL + 128 * FSTR)
#define SM_BL (SM_BH + 64 * FSTR)
#define FUSE_SMEM ((SM_BL + 64 * FSTR) * 2)

__global__ __launch_bounds__(256, 2) void fuse_mma_kernel(
    const float* __restrict__ bf, float* __restrict__ C)
{
    extern __shared__ unsigned short fsm[];
    unsigned short* sAh = fsm + SM_AH;
    unsigned short* sAl = fsm + SM_AL;
    unsigned short* sBh = fsm + SM_BH;
    unsigned short* sBl = fsm + SM_BL;

    int tid = threadIdx.x;
    int wid = tid >> 5;
    int lane = tid & 31;
    int g = lane >> 2;
    int t = lane & 3;
    int wm = wid >> 1;
    int wn = wid & 1;

    int n0 = blockIdx.x * 64;
    int m0 = blockIdx.y * 128;

    float acc[2][4][4];
    #pragma unroll
    for (int mt = 0; mt < 2; mt++)
        #pragma unroll
        for (int nt = 0; nt < 4; nt++)
            #pragma unroll
            for (int r = 0; r < 4; r++) acc[mt][nt][r] = 0.0f;

    for (int k0 = 0; k0 < DD; k0 += 64) {
        for (int i = tid; i < 1024; i += 256) {
            int row = i >> 3, c8 = i & 7;
            size_t ga = (size_t)(m0 + row) * DD + k0 + c8 * 8;
            *reinterpret_cast<uint4*>(&sAh[row * FSTR + c8 * 8]) =
                *reinterpret_cast<const uint4*>(g_Ah + ga);
            *reinterpret_cast<uint4*>(&sAl[row * FSTR + c8 * 8]) =
                *reinterpret_cast<const uint4*>(g_Al + ga);
        }
        for (int i = tid; i < 512; i += 256) {
            int row = i >> 3, c8 = i & 7;
            size_t gb = (size_t)(n0 + row) * DD + k0 + c8 * 8;
            *reinterpret_cast<uint4*>(&sBh[row * FSTR + c8 * 8]) =
                *reinterpret_cast<const uint4*>(g_Wh + gb);
            *reinterpret_cast<uint4*>(&sBl[row * FSTR + c8 * 8]) =
                *reinterpret_cast<const uint4*>(g_Wl + gb);
        }
        __syncthreads();

        #pragma unroll
        for (int ks = 0; ks < 4; ks++) {
            int k = ks * 16;
            uint32_t ah[2][4], al[2][4];
            #pragma unroll
            for (int mt = 0; mt < 2; mt++) {
                int r0 = (wm * 32 + mt * 16 + g) * FSTR + k + t * 2;
                int r1 = r0 + 8 * FSTR;
                ah[mt][0] = *reinterpret_cast<const uint32_t*>(&sAh[r0]);
                ah[mt][1] = *reinterpret_cast<const uint32_t*>(&sAh[r1]);
                ah[mt][2] = *reinterpret_cast<const uint32_t*>(&sAh[r0 + 8]);
                ah[mt][3] = *reinterpret_cast<const uint32_t*>(&sAh[r1 + 8]);
                al[mt][0] = *reinterpret_cast<const uint32_t*>(&sAl[r0]);
                al[mt][1] = *reinterpret_cast<const uint32_t*>(&sAl[r1]);
                al[mt][2] = *reinterpret_cast<const uint32_t*>(&sAl[r0 + 8]);
                al[mt][3] = *reinterpret_cast<const uint32_t*>(&sAl[r1 + 8]);
            }
            uint32_t bh[4][2], blo[4][2];
            #pragma unroll
            for (int nt = 0; nt < 4; nt++) {
                int r0 = (wn * 32 + nt * 8 + g) * FSTR + k + t * 2;
                bh[nt][0]  = *reinterpret_cast<const uint32_t*>(&sBh[r0]);
                bh[nt][1]  = *reinterpret_cast<const uint32_t*>(&sBh[r0 + 8]);
                blo[nt][0] = *reinterpret_cast<const uint32_t*>(&sBl[r0]);
                blo[nt][1] = *reinterpret_cast<const uint32_t*>(&sBl[r0 + 8]);
            }
            #pragma unroll
            for (int mt = 0; mt < 2; mt++)
                #pragma unroll
                for (int nt = 0; nt < 4; nt++) {
                    mma16816(acc[mt][nt], ah[mt], bh[nt]);
                    mma16816(acc[mt][nt], ah[mt], blo[nt]);
                    mma16816(acc[mt][nt], al[mt], bh[nt]);
                }
        }
        __syncthreads();
    }

    #pragma unroll
    for (int nt = 0; nt < 4; nt++) {
        int n = n0 + wn * 32 + nt * 8 + t * 2;
        float b0 = bf[n], b1 = bf[n + 1];
        #pragma unroll
        for (int mt = 0; mt < 2; mt++) {
            int m = m0 + wm * 32 + mt * 16 + g;
            float2 v0 = make_float2(acc[mt][nt][0] + b0, acc[mt][nt][1] + b1);
            float2 v1 = make_float2(acc[mt][nt][2] + b0, acc[mt][nt][3] + b1);
            *reinterpret_cast<float2*>(C + (size_t)m * DD + n) = v0;
            *reinterpret_cast<float2*>(C + (size_t)(m + 8) * DD + n) = v1;
        }
    }
}

// ---------------------------------------------------------------------------
extern "C" void kernel_launch(void* const* d_in, const int* in_sizes, int n_in,
                              void* d_out, int out_size)
{
    const float* X    = (const float*)d_in[0];
    const int*   mask = (const int*)  d_in[1];
    const float* Wq   = (const float*)d_in[2];
    const float* bq   = (const float*)d_in[3];
    const float* Wk   = (const float*)d_in[4];
    const float* bk   = (const float*)d_in[5];
    const float* Wv   = (const float*)d_in[6];
    const float* bv   = (const float*)d_in[7];
    const float* Wf   = (const float*)d_in[8];
    const float* bf   = (const float*)d_in[9];
    float* out = (float*)d_out;

    cudaFuncSetAttribute(attn_mma_kernel,
                         cudaFuncAttributeMaxDynamicSharedMemorySize, ATTN_SMEM);
    cudaFuncSetAttribute(fuse_mma_kernel,
                         cudaFuncAttributeMaxDynamicSharedMemorySize, FUSE_SMEM);

    dim3 grid1(TT / 64, BB * HH);
    qkv_kernel<<<grid1, 256>>>(X, Wq, bq, Wk, bk, Wv, bv);

    convW_kernel<<<dim3(32, 32), 256>>>(Wf);

    dim3 grid2(TT / 128, BB * HH);
    attn_mma_kernel<<<grid2, 128, ATTN_SMEM>>>(mask);

    dim3 grid4(DD / 64, (BB * TT) / 128);
    fuse_mma_kernel<<<grid4, 256, FUSE_SMEM>>>(bf, out);
}

// round 7
// speedup vs baseline: 7.5627x; 1.0656x over previous
#include <cuda_runtime.h>
#include <cuda_bf16.h>
#include <cstdint>

#define BB 8
#define TT 512
#define DD 1024
#define HH 16
#define DH 64

// bf16 hi/lo splits (device globals; no allocs allowed)
__device__ unsigned short g_Qh[BB * HH * TT * DH];   // [bh][t][d]  (Q pre-scaled by 1/8)
__device__ unsigned short g_Ql[BB * HH * TT * DH];
__device__ unsigned short g_Kh[BB * HH * TT * DH];   // [bh][t][d]
__device__ unsigned short g_Kl[BB * HH * TT * DH];
__device__ unsigned short g_Vh[BB * HH * DH * TT];   // [bh][d][t]
__device__ unsigned short g_Vl[BB * HH * DH * TT];
__device__ unsigned short g_Ah[BB * TT * DD];        // attention out split [m][k]
__device__ unsigned short g_Al[BB * TT * DD];
__device__ unsigned short g_Wh[DD * DD];             // W^T: [n][k]
__device__ unsigned short g_Wl[DD * DD];

__device__ __forceinline__ void mma16816(float* c, const uint32_t* a, const uint32_t* b) {
    asm volatile(
        "mma.sync.aligned.m16n8k16.row.col.f32.bf16.bf16.f32 "
        "{%0,%1,%2,%3}, {%4,%5,%6,%7}, {%8,%9}, {%0,%1,%2,%3};"
        : "+f"(c[0]), "+f"(c[1]), "+f"(c[2]), "+f"(c[3])
        : "r"(a[0]), "r"(a[1]), "r"(a[2]), "r"(a[3]), "r"(b[0]), "r"(b[1]));
}

__device__ __forceinline__ void fsplit(float v, unsigned short& h, unsigned short& l) {
    uint32_t b = __float_as_uint(v);
    h = (unsigned short)(b >> 16);
    float lo = v - __uint_as_float(b & 0xFFFF0000u);
    uint32_t p;
    asm("cvt.rn.bf16x2.f32 %0, %1, %2;" : "=r"(p) : "f"(lo), "f"(lo));
    l = (unsigned short)(p & 0xFFFF);
}

__device__ __forceinline__ void cp16(unsigned short* sdst, const unsigned short* gsrc) {
    uint32_t s = (uint32_t)__cvta_generic_to_shared(sdst);
    asm volatile("cp.async.cg.shared.global [%0], [%1], 16;" :: "r"(s), "l"(gsrc));
}
#define CP_COMMIT() asm volatile("cp.async.commit_group;" ::: "memory")
#define CP_WAIT1()  asm volatile("cp.async.wait_group 1;" ::: "memory")

// ---------------------------------------------------------------------------
// Kernel 1: QKV projections -> bf16 hi/lo splits in MMA layouts. (unchanged)
// ---------------------------------------------------------------------------
__global__ __launch_bounds__(256) void qkv_kernel(
    const float* __restrict__ X,
    const float* __restrict__ Wq, const float* __restrict__ bq,
    const float* __restrict__ Wk, const float* __restrict__ bk,
    const float* __restrict__ Wv, const float* __restrict__ bv)
{
    __shared__ float Xs[64 * 65];
    __shared__ float Ws[64 * 64];

    int bh = blockIdx.y;
    int b  = bh >> 4;
    int h  = bh & 15;
    int t0 = blockIdx.x * 64;
    int tid = threadIdx.x;
    int tn = tid & 15;
    int tm = tid >> 4;

    const float* Xb = X + ((size_t)(b * TT + t0)) * DD + h * DH;
    for (int i = tid; i < 1024; i += 256) {
        int t = i >> 4, d4 = (i & 15) * 4;
        float4 v = *reinterpret_cast<const float4*>(Xb + (size_t)t * DD + d4);
        Xs[(d4 + 0) * 65 + t] = v.x;
        Xs[(d4 + 1) * 65 + t] = v.y;
        Xs[(d4 + 2) * 65 + t] = v.z;
        Xs[(d4 + 3) * 65 + t] = v.w;
    }

    const float* Wl[3] = {Wq, Wk, Wv};
    const float* bl[3] = {bq, bk, bv};

    for (int p = 0; p < 3; p++) {
        __syncthreads();
        const float* W = Wl[p] + h * DH * DH;
        for (int i = tid; i < 1024; i += 256) {
            int d = i >> 4, e4 = (i & 15) * 4;
            *reinterpret_cast<float4*>(&Ws[d * 64 + e4]) =
                *reinterpret_cast<const float4*>(W + d * 64 + e4);
        }
        __syncthreads();

        float acc[4][4];
        #pragma unroll
        for (int j = 0; j < 4; j++)
            #pragma unroll
            for (int i = 0; i < 4; i++) acc[j][i] = 0.0f;

        #pragma unroll 8
        for (int d = 0; d < 64; d++) {
            float a[4], bb[4];
            #pragma unroll
            for (int j = 0; j < 4; j++) a[j] = Ws[d * 64 + tm * 4 + j];
            #pragma unroll
            for (int i = 0; i < 4; i++) bb[i] = Xs[d * 65 + tn + 16 * i];
            #pragma unroll
            for (int j = 0; j < 4; j++)
                #pragma unroll
                for (int i = 0; i < 4; i++)
                    acc[j][i] += a[j] * bb[i];
        }

        const float* bias = bl[p] + h * DH;
        float qscale = (p == 0) ? 0.125f : 1.0f;

        __syncthreads();
        unsigned short* sH = reinterpret_cast<unsigned short*>(Ws);
        unsigned short* sL = sH + 4096;

        #pragma unroll
        for (int j = 0; j < 4; j++) {
            int e = tm * 4 + j;
            float be = bias[e];
            #pragma unroll
            for (int i = 0; i < 4; i++) {
                int t = tn + 16 * i;
                float v = (acc[j][i] + be) * qscale;
                unsigned short hh, ll;
                fsplit(v, hh, ll);
                int idx = (p < 2) ? (t * 64 + e) : (e * 64 + t);
                sH[idx] = hh;
                sL[idx] = ll;
            }
        }
        __syncthreads();

        unsigned short* Hd;
        unsigned short* Ld;
        if (p == 0)      { Hd = g_Qh; Ld = g_Ql; }
        else if (p == 1) { Hd = g_Kh; Ld = g_Kl; }
        else             { Hd = g_Vh; Ld = g_Vl; }

        for (int i = tid; i < 512; i += 256) {
            int row = i >> 3, c8 = (i & 7) * 8;
            uint4 vh = reinterpret_cast<const uint4*>(sH)[i];
            uint4 vl = reinterpret_cast<const uint4*>(sL)[i];
            size_t off;
            if (p < 2) off = ((size_t)bh * TT + t0 + row) * DH + c8;
            else       off = ((size_t)bh * DH + row) * TT + t0 + c8;
            *reinterpret_cast<uint4*>(Hd + off) = vh;
            *reinterpret_cast<uint4*>(Ld + off) = vl;
        }
    }
}

// ---------------------------------------------------------------------------
// Kernel 2: flash attention via mma.sync, 256 threads (8 warps, 16q each),
// K/V double-buffered with cp.async.
// ---------------------------------------------------------------------------
#define ASTR 72
#define AQ_H 0
#define AQ_L (AQ_H + 128 * ASTR)               // 9216
#define AKV  (AQ_L + 128 * ASTR)               // stages start (18432)
#define AKV_STG (4 * 64 * ASTR)                // 18432 ushorts per stage
#define A_MSK (AKV + 2 * AKV_STG)              // mask after 2 stages
#define ATTN_SMEM ((A_MSK + 1024) * 2)

__global__ __launch_bounds__(256) void attn_mma_kernel(const int* __restrict__ mask)
{
    extern __shared__ unsigned short shm[];
    unsigned short* sQh = shm + AQ_H;
    unsigned short* sQl = shm + AQ_L;
    int* sMask = (int*)(shm + A_MSK);

    int tid = threadIdx.x;
    int wid = tid >> 5;
    int lane = tid & 31;
    int g = lane >> 2;
    int t = lane & 3;
    int wq = wid * 16;

    int bh = blockIdx.y;
    int b  = bh >> 4;
    int h  = bh & 15;
    int q0 = blockIdx.x * 128;

    // load Q tiles (regular loads; barrier before first compute covers them)
    {
        const unsigned short* Qhg = g_Qh + ((size_t)bh * TT + q0) * DH;
        const unsigned short* Qlg = g_Ql + ((size_t)bh * TT + q0) * DH;
        for (int i = tid; i < 1024; i += 256) {
            int row = i >> 3, c8 = (i & 7) * 8;
            *reinterpret_cast<uint4*>(&sQh[row * ASTR + c8]) =
                *reinterpret_cast<const uint4*>(Qhg + row * DH + c8);
            *reinterpret_cast<uint4*>(&sQl[row * ASTR + c8]) =
                *reinterpret_cast<const uint4*>(Qlg + row * DH + c8);
        }
        for (int i = tid; i < TT; i += 256) sMask[i] = mask[b * TT + i];
    }

    // prologue: stage 0 K/V loads
    auto load_kv = [&](int stage, int kb) {
        unsigned short* stg = shm + AKV + stage * AKV_STG;
        for (int i = tid; i < 512; i += 256) {
            int row = i >> 3, c8 = (i & 7) * 8;
            size_t ko = ((size_t)bh * TT + kb + row) * DH + c8;
            size_t vo = ((size_t)bh * DH + row) * TT + kb + c8;
            cp16(stg + row * ASTR + c8,                 g_Kh + ko);
            cp16(stg + 4608 + row * ASTR + c8,          g_Kl + ko);
            cp16(stg + 9216 + row * ASTR + c8,          g_Vh + vo);
            cp16(stg + 13824 + row * ASTR + c8,         g_Vl + vo);
        }
    };
    load_kv(0, 0);
    CP_COMMIT();

    float O[8][4];
    float m_[2], l_[2];
    m_[0] = m_[1] = -1e30f;
    l_[0] = l_[1] = 0.0f;
    #pragma unroll
    for (int nt = 0; nt < 8; nt++)
        #pragma unroll
        for (int r = 0; r < 4; r++) O[nt][r] = 0.0f;

    for (int kt = 0; kt < 8; kt++) {
        int kb = kt * 64;
        if (kt + 1 < 8) load_kv((kt + 1) & 1, kb + 64);
        CP_COMMIT();
        CP_WAIT1();
        __syncthreads();

        unsigned short* stg = shm + AKV + (kt & 1) * AKV_STG;
        unsigned short* sKh = stg;
        unsigned short* sKl = stg + 4608;
        unsigned short* sVh = stg + 9216;
        unsigned short* sVl = stg + 13824;

        // ---- S = Q K^T (3-term split) ----
        float S[8][4];
        #pragma unroll
        for (int nt = 0; nt < 8; nt++)
            #pragma unroll
            for (int r = 0; r < 4; r++) S[nt][r] = 0.0f;

        #pragma unroll
        for (int ks = 0; ks < 4; ks++) {
            uint32_t qh[4], ql[4];
            {
                int base = (wq + g) * ASTR + ks * 16 + t * 2;
                qh[0] = *reinterpret_cast<const uint32_t*>(&sQh[base]);
                qh[1] = *reinterpret_cast<const uint32_t*>(&sQh[base + 8 * ASTR]);
                qh[2] = *reinterpret_cast<const uint32_t*>(&sQh[base + 8]);
                qh[3] = *reinterpret_cast<const uint32_t*>(&sQh[base + 8 * ASTR + 8]);
                ql[0] = *reinterpret_cast<const uint32_t*>(&sQl[base]);
                ql[1] = *reinterpret_cast<const uint32_t*>(&sQl[base + 8 * ASTR]);
                ql[2] = *reinterpret_cast<const uint32_t*>(&sQl[base + 8]);
                ql[3] = *reinterpret_cast<const uint32_t*>(&sQl[base + 8 * ASTR + 8]);
            }
            uint32_t kh[8][2], kl[8][2];
            #pragma unroll
            for (int nt = 0; nt < 8; nt++) {
                int kb2 = (nt * 8 + g) * ASTR + ks * 16 + t * 2;
                kh[nt][0] = *reinterpret_cast<const uint32_t*>(&sKh[kb2]);
                kh[nt][1] = *reinterpret_cast<const uint32_t*>(&sKh[kb2 + 8]);
                kl[nt][0] = *reinterpret_cast<const uint32_t*>(&sKl[kb2]);
                kl[nt][1] = *reinterpret_cast<const uint32_t*>(&sKl[kb2 + 8]);
            }
            #pragma unroll
            for (int nt = 0; nt < 8; nt++) {
                mma16816(S[nt], qh, kh[nt]);
                mma16816(S[nt], qh, kl[nt]);
                mma16816(S[nt], ql, kh[nt]);
            }
        }

        // ---- mask + online softmax ----
        #pragma unroll
        for (int nt = 0; nt < 8; nt++) {
            int mk0 = sMask[kb + nt * 8 + 2 * t];
            int mk1 = sMask[kb + nt * 8 + 2 * t + 1];
            if (mk0 <= 0) { S[nt][0] = -1e9f; S[nt][2] = -1e9f; }
            if (mk1 <= 0) { S[nt][1] = -1e9f; S[nt][3] = -1e9f; }
        }
        #pragma unroll
        for (int r = 0; r < 2; r++) {
            float mx = -1e30f;
            #pragma unroll
            for (int nt = 0; nt < 8; nt++) {
                mx = fmaxf(mx, S[nt][2 * r]);
                mx = fmaxf(mx, S[nt][2 * r + 1]);
            }
            mx = fmaxf(mx, __shfl_xor_sync(0xffffffffu, mx, 1));
            mx = fmaxf(mx, __shfl_xor_sync(0xffffffffu, mx, 2));
            float mnew  = fmaxf(m_[r], mx);
            float alpha = __expf(m_[r] - mnew);
            float rs = 0.0f;
            #pragma unroll
            for (int nt = 0; nt < 8; nt++) {
                float e0 = __expf(S[nt][2 * r]     - mnew);
                float e1 = __expf(S[nt][2 * r + 1] - mnew);
                S[nt][2 * r]     = e0;
                S[nt][2 * r + 1] = e1;
                rs += e0 + e1;
            }
            rs += __shfl_xor_sync(0xffffffffu, rs, 1);
            rs += __shfl_xor_sync(0xffffffffu, rs, 2);
            l_[r] = l_[r] * alpha + rs;
            m_[r] = mnew;
            #pragma unroll
            for (int nt = 0; nt < 8; nt++) {
                O[nt][2 * r]     *= alpha;
                O[nt][2 * r + 1] *= alpha;
            }
        }

        // ---- O += P V (3-term split) ----
        #pragma unroll
        for (int ks = 0; ks < 4; ks++) {
            uint32_t ph[4], pl[4];
            #pragma unroll
            for (int half = 0; half < 2; half++) {
                const float* sv = S[2 * ks + half];
                uint32_t b0 = __float_as_uint(sv[0]);
                uint32_t b1 = __float_as_uint(sv[1]);
                uint32_t b2 = __float_as_uint(sv[2]);
                uint32_t b3 = __float_as_uint(sv[3]);
                ph[2 * half]     = __byte_perm(b0, b1, 0x7632);
                ph[2 * half + 1] = __byte_perm(b2, b3, 0x7632);
                float l0 = sv[0] - __uint_as_float(b0 & 0xFFFF0000u);
                float l1 = sv[1] - __uint_as_float(b1 & 0xFFFF0000u);
                float l2 = sv[2] - __uint_as_float(b2 & 0xFFFF0000u);
                float l3 = sv[3] - __uint_as_float(b3 & 0xFFFF0000u);
                asm("cvt.rn.bf16x2.f32 %0, %1, %2;"
                    : "=r"(pl[2 * half]) : "f"(l1), "f"(l0));
                asm("cvt.rn.bf16x2.f32 %0, %1, %2;"
                    : "=r"(pl[2 * half + 1]) : "f"(l3), "f"(l2));
            }
            uint32_t vh[8][2], vl[8][2];
            #pragma unroll
            for (int nt = 0; nt < 8; nt++) {
                int vo = (nt * 8 + g) * ASTR + ks * 16 + t * 2;
                vh[nt][0] = *reinterpret_cast<const uint32_t*>(&sVh[vo]);
                vh[nt][1] = *reinterpret_cast<const uint32_t*>(&sVh[vo + 8]);
                vl[nt][0] = *reinterpret_cast<const uint32_t*>(&sVl[vo]);
                vl[nt][1] = *reinterpret_cast<const uint32_t*>(&sVl[vo + 8]);
            }
            #pragma unroll
            for (int nt = 0; nt < 8; nt++) {
                mma16816(O[nt], ph, vh[nt]);
                mma16816(O[nt], ph, vl[nt]);
                mma16816(O[nt], pl, vh[nt]);
            }
        }
        __syncthreads();
    }

    // epilogue: normalize, split to bf16 hi/lo, write g_Ah/g_Al
    #pragma unroll
    for (int r = 0; r < 2; r++) {
        float inv = 1.0f / l_[r];
        int mrow = b * TT + q0 + wq + g + 8 * r;
        size_t base = (size_t)mrow * DD + h * DH;
        #pragma unroll
        for (int nt = 0; nt < 8; nt++) {
            float v0 = O[nt][2 * r]     * inv;
            float v1 = O[nt][2 * r + 1] * inv;
            uint32_t b0 = __float_as_uint(v0), b1 = __float_as_uint(v1);
            uint32_t hp = __byte_perm(b0, b1, 0x7632);
            float l0 = v0 - __uint_as_float(b0 & 0xFFFF0000u);
            float l1 = v1 - __uint_as_float(b1 & 0xFFFF0000u);
            uint32_t lp;
            asm("cvt.rn.bf16x2.f32 %0, %1, %2;" : "=r"(lp) : "f"(l1), "f"(l0));
            *reinterpret_cast<uint32_t*>(g_Ah + base + nt * 8 + 2 * t) = hp;
            *reinterpret_cast<uint32_t*>(g_Al + base + nt * 8 + 2 * t) = lp;
        }
    }
}

// ---------------------------------------------------------------------------
// Kernel 3: Wf [k][n] fp32 -> g_Wh/g_Wl [n][k] bf16 (transpose + split)
// ---------------------------------------------------------------------------
__global__ __launch_bounds__(256) void convW_kernel(const float* __restrict__ Wf)
{
    __shared__ float t[32][33];
    int k0 = blockIdx.x * 32, n0 = blockIdx.y * 32;
    int tx = threadIdx.x & 31, ty = threadIdx.x >> 5;
    #pragma unroll
    for (int j = 0; j < 4; j++)
        t[ty + 8 * j][tx] = Wf[(size_t)(k0 + ty + 8 * j) * DD + n0 + tx];
    __syncthreads();
    #pragma unroll
    for (int j = 0; j < 4; j++) {
        int k = k0 + tx, n = n0 + ty + 8 * j;
        float v = t[tx][ty + 8 * j];
        unsigned short hh, ll;
        fsplit(v, hh, ll);
        g_Wh[(size_t)n * DD + k] = hh;
        g_Wl[(size_t)n * DD + k] = ll;
    }
}

// ---------------------------------------------------------------------------
// Kernel 4: fusion GEMM via mma.sync, 3-stage cp.async pipeline, BK=32.
// CTA 128m x 64n, 8 warps (4m x 2n), warp 32m x 32n.
// ---------------------------------------------------------------------------
#define F2 40
#define FST_A  (128 * F2)          // 5120 ushorts per A matrix
#define FST_B  (64 * F2)           // 2560 ushorts per B matrix
#define FST_SZ (2 * FST_A + 2 * FST_B)   // 15360 ushorts per stage
#define FNST 3
#define FUSE_SMEM (FNST * FST_SZ * 2)    // 92160 bytes

__global__ __launch_bounds__(256, 2) void fuse_mma_kernel(
    const float* __restrict__ bf, float* __restrict__ C)
{
    extern __shared__ unsigned short fsm[];

    int tid = threadIdx.x;
    int wid = tid >> 5;
    int lane = tid & 31;
    int g = lane >> 2;
    int t = lane & 3;
    int wm = wid >> 1;
    int wn = wid & 1;

    int n0 = blockIdx.x * 64;
    int m0 = blockIdx.y * 128;

    auto load_stage = [&](int stage, int k0) {
        unsigned short* st = fsm + stage * FST_SZ;
        for (int i = tid; i < 512; i += 256) {
            int row = i >> 2, c = (i & 3) * 8;
            size_t ga = (size_t)(m0 + row) * DD + k0 + c;
            cp16(st + row * F2 + c,          g_Ah + ga);
            cp16(st + FST_A + row * F2 + c,  g_Al + ga);
        }
        for (int i = tid; i < 256; i += 256) {
            int row = i >> 2, c = (i & 3) * 8;
            size_t gb = (size_t)(n0 + row) * DD + k0 + c;
            cp16(st + 2 * FST_A + row * F2 + c,          g_Wh + gb);
            cp16(st + 2 * FST_A + FST_B + row * F2 + c,  g_Wl + gb);
        }
    };

    float acc[2][4][4];
    #pragma unroll
    for (int mt = 0; mt < 2; mt++)
        #pragma unroll
        for (int nt = 0; nt < 4; nt++)
            #pragma unroll
            for (int r = 0; r < 4; r++) acc[mt][nt][r] = 0.0f;

    load_stage(0, 0);
    CP_COMMIT();
    load_stage(1, 32);
    CP_COMMIT();

    for (int kt = 0; kt < 32; kt++) {
        CP_WAIT1();
        __syncthreads();

        unsigned short* st = fsm + (kt % 3) * FST_SZ;
        unsigned short* sAh = st;
        unsigned short* sAl = st + FST_A;
        unsigned short* sBh = st + 2 * FST_A;
        unsigned short* sBl = st + 2 * FST_A + FST_B;

        #pragma unroll
        for (int ks = 0; ks < 2; ks++) {
            int k = ks * 16;
            uint32_t ah[2][4], al[2][4];
            #pragma unroll
            for (int mt = 0; mt < 2; mt++) {
                int r0 = (wm * 32 + mt * 16 + g) * F2 + k + t * 2;
                int r1 = r0 + 8 * F2;
                ah[mt][0] = *reinterpret_cast<const uint32_t*>(&sAh[r0]);
                ah[mt][1] = *reinterpret_cast<const uint32_t*>(&sAh[r1]);
                ah[mt][2] = *reinterpret_cast<const uint32_t*>(&sAh[r0 + 8]);
                ah[mt][3] = *reinterpret_cast<const uint32_t*>(&sAh[r1 + 8]);
                al[mt][0] = *reinterpret_cast<const uint32_t*>(&sAl[r0]);
                al[mt][1] = *reinterpret_cast<const uint32_t*>(&sAl[r1]);
                al[mt][2] = *reinterpret_cast<const uint32_t*>(&sAl[r0 + 8]);
                al[mt][3] = *reinterpret_cast<const uint32_t*>(&sAl[r1 + 8]);
            }
            uint32_t bh[4][2], blo[4][2];
            #pragma unroll
            for (int nt = 0; nt < 4; nt++) {
                int r0 = (wn * 32 + nt * 8 + g) * F2 + k + t * 2;
                bh[nt][0]  = *reinterpret_cast<const uint32_t*>(&sBh[r0]);
                bh[nt][1]  = *reinterpret_cast<const uint32_t*>(&sBh[r0 + 8]);
                blo[nt][0] = *reinterpret_cast<const uint32_t*>(&sBl[r0]);
                blo[nt][1] = *reinterpret_cast<const uint32_t*>(&sBl[r0 + 8]);
            }
            #pragma unroll
            for (int mt = 0; mt < 2; mt++)
                #pragma unroll
                for (int nt = 0; nt < 4; nt++) {
                    mma16816(acc[mt][nt], ah[mt], bh[nt]);
                    mma16816(acc[mt][nt], ah[mt], blo[nt]);
                    mma16816(acc[mt][nt], al[mt], bh[nt]);
                }
        }
        __syncthreads();

        if (kt + 2 < 32) load_stage((kt + 2) % 3, (kt + 2) * 32);
        CP_COMMIT();
    }

    #pragma unroll
    for (int nt = 0; nt < 4; nt++) {
        int n = n0 + wn * 32 + nt * 8 + t * 2;
        float b0 = bf[n], b1 = bf[n + 1];
        #pragma unroll
        for (int mt = 0; mt < 2; mt++) {
            int m = m0 + wm * 32 + mt * 16 + g;
            float2 v0 = make_float2(acc[mt][nt][0] + b0, acc[mt][nt][1] + b1);
            float2 v1 = make_float2(acc[mt][nt][2] + b0, acc[mt][nt][3] + b1);
            *reinterpret_cast<float2*>(C + (size_t)m * DD + n) = v0;
            *reinterpret_cast<float2*>(C + (size_t)(m + 8) * DD + n) = v1;
        }
    }
}

// ---------------------------------------------------------------------------
extern "C" void kernel_launch(void* const* d_in, const int* in_sizes, int n_in,
                              void* d_out, int out_size)
{
    const float* X    = (const float*)d_in[0];
    const int*   mask = (const int*)  d_in[1];
    const float* Wq   = (const float*)d_in[2];
    const float* bq   = (const float*)d_in[3];
    const float* Wk   = (const float*)d_in[4];
    const float* bk   = (const float*)d_in[5];
    const float* Wv   = (const float*)d_in[6];
    const float* bv   = (const float*)d_in[7];
    const float* Wf   = (const float*)d_in[8];
    const float* bf   = (const float*)d_in[9];
    float* out = (float*)d_out;

    cudaFuncSetAttribute(attn_mma_kernel,
                         cudaFuncAttributeMaxDynamicSharedMemorySize, ATTN_SMEM);
    cudaFuncSetAttribute(fuse_mma_kernel,
                         cudaFuncAttributeMaxDynamicSharedMemorySize, FUSE_SMEM);

    dim3 grid1(TT / 64, BB * HH);
    qkv_kernel<<<grid1, 256>>>(X, Wq, bq, Wk, bk, Wv, bv);

    convW_kernel<<<dim3(32, 32), 256>>>(Wf);

    dim3 grid2(TT / 128, BB * HH);
    attn_mma_kernel<<<grid2, 256, ATTN_SMEM>>>(mask);

    dim3 grid4(DD / 64, (BB * TT) / 128);
    fuse_mma_kernel<<<grid4, 256, FUSE_SMEM>>>(bf, out);
}

// round 8
// speedup vs baseline: 8.9217x; 1.1797x over previous
#include <cuda_runtime.h>
#include <cuda_bf16.h>
#include <cstdint>

#define BB 8
#define TT 512
#define DD 1024
#define HH 16
#define DH 64

// bf16 hi/lo splits (device globals; no allocs allowed)
__device__ unsigned short g_Qh[BB * HH * TT * DH];   // [bh][t][d]  (Q pre-scaled by 1/8)
__device__ unsigned short g_Ql[BB * HH * TT * DH];
__device__ unsigned short g_Kh[BB * HH * TT * DH];   // [bh][t][d]
__device__ unsigned short g_Kl[BB * HH * TT * DH];
__device__ unsigned short g_Vh[BB * HH * DH * TT];   // [bh][d][t]
__device__ unsigned short g_Vl[BB * HH * DH * TT];
__device__ unsigned short g_Ah[BB * TT * DD];        // attention out split [m][k]
__device__ unsigned short g_Al[BB * TT * DD];
__device__ unsigned short g_Wh[DD * DD];             // W^T: [n][k]
__device__ unsigned short g_Wl[DD * DD];

__device__ __forceinline__ void mma16816(float* c, const uint32_t* a, const uint32_t* b) {
    asm volatile(
        "mma.sync.aligned.m16n8k16.row.col.f32.bf16.bf16.f32 "
        "{%0,%1,%2,%3}, {%4,%5,%6,%7}, {%8,%9}, {%0,%1,%2,%3};"
        : "+f"(c[0]), "+f"(c[1]), "+f"(c[2]), "+f"(c[3])
        : "r"(a[0]), "r"(a[1]), "r"(a[2]), "r"(a[3]), "r"(b[0]), "r"(b[1]));
}

__device__ __forceinline__ void ldm_x4(uint32_t* r, uint32_t saddr) {
    asm volatile("ldmatrix.sync.aligned.m8n8.x4.shared.b16 {%0,%1,%2,%3}, [%4];"
        : "=r"(r[0]), "=r"(r[1]), "=r"(r[2]), "=r"(r[3]) : "r"(saddr));
}

__device__ __forceinline__ void fsplit(float v, unsigned short& h, unsigned short& l) {
    uint32_t b = __float_as_uint(v);
    h = (unsigned short)(b >> 16);
    float lo = v - __uint_as_float(b & 0xFFFF0000u);
    uint32_t p;
    asm("cvt.rn.bf16x2.f32 %0, %1, %2;" : "=r"(p) : "f"(lo), "f"(lo));
    l = (unsigned short)(p & 0xFFFF);
}

__device__ __forceinline__ void cp16(unsigned short* sdst, const unsigned short* gsrc) {
    uint32_t s = (uint32_t)__cvta_generic_to_shared(sdst);
    asm volatile("cp.async.cg.shared.global [%0], [%1], 16;" :: "r"(s), "l"(gsrc));
}
#define CP_COMMIT() asm volatile("cp.async.commit_group;" ::: "memory")
#define CP_WAIT1()  asm volatile("cp.async.wait_group 1;" ::: "memory")

// ---------------------------------------------------------------------------
// Kernel 1: QKV projections, single-pass (all 3 weights resident),
// outputs bf16 hi/lo splits. grid (T/64, B*H), 256 threads.
// ---------------------------------------------------------------------------
#define QKV_XS   0                     // 64*65 floats
#define QKV_W3   (64 * 65)             // 3*64*64 floats (also output staging)
#define QKV_SMEM ((QKV_W3 + 3 * 64 * 64) * 4)

__global__ __launch_bounds__(256) void qkv_kernel(
    const float* __restrict__ X,
    const float* __restrict__ Wq, const float* __restrict__ bq,
    const float* __restrict__ Wk, const float* __restrict__ bk,
    const float* __restrict__ Wv, const float* __restrict__ bv)
{
    extern __shared__ float qsm[];
    float* Xs = qsm + QKV_XS;
    float* W3 = qsm + QKV_W3;

    int bh = blockIdx.y;
    int b  = bh >> 4;
    int h  = bh & 15;
    int t0 = blockIdx.x * 64;
    int tid = threadIdx.x;
    int tn = tid & 15;
    int tm = tid >> 4;

    const float* Xb = X + ((size_t)(b * TT + t0)) * DD + h * DH;
    for (int i = tid; i < 1024; i += 256) {
        int t = i >> 4, d4 = (i & 15) * 4;
        float4 v = *reinterpret_cast<const float4*>(Xb + (size_t)t * DD + d4);
        Xs[(d4 + 0) * 65 + t] = v.x;
        Xs[(d4 + 1) * 65 + t] = v.y;
        Xs[(d4 + 2) * 65 + t] = v.z;
        Xs[(d4 + 3) * 65 + t] = v.w;
    }
    {
        const float* Wsrc[3] = {Wq + h * DH * DH, Wk + h * DH * DH, Wv + h * DH * DH};
        for (int p = 0; p < 3; p++)
            for (int i = tid; i < 1024; i += 256)
                *reinterpret_cast<float4*>(&W3[p * 4096 + i * 4]) =
                    *reinterpret_cast<const float4*>(Wsrc[p] + i * 4);
    }
    __syncthreads();

    float acc[3][4][4];
    #pragma unroll
    for (int p = 0; p < 3; p++)
        #pragma unroll
        for (int j = 0; j < 4; j++)
            #pragma unroll
            for (int i = 0; i < 4; i++) acc[p][j][i] = 0.0f;

    #pragma unroll 4
    for (int d = 0; d < 64; d++) {
        float bb[4];
        #pragma unroll
        for (int i = 0; i < 4; i++) bb[i] = Xs[d * 65 + tn + 16 * i];
        #pragma unroll
        for (int p = 0; p < 3; p++) {
            float a[4];
            #pragma unroll
            for (int j = 0; j < 4; j++) a[j] = W3[p * 4096 + d * 64 + tm * 4 + j];
            #pragma unroll
            for (int j = 0; j < 4; j++)
                #pragma unroll
                for (int i = 0; i < 4; i++)
                    acc[p][j][i] += a[j] * bb[i];
        }
    }
    __syncthreads();   // done reading W3 -> reuse as ushort staging (3 x (hi+lo))

    unsigned short* stg = reinterpret_cast<unsigned short*>(W3);
    const float* bl[3] = {bq, bk, bv};
    #pragma unroll
    for (int p = 0; p < 3; p++) {
        unsigned short* sH = stg + p * 8192;
        unsigned short* sL = sH + 4096;
        float qscale = (p == 0) ? 0.125f : 1.0f;
        #pragma unroll
        for (int j = 0; j < 4; j++) {
            int e = tm * 4 + j;
            float be = bl[p][h * DH + e];
            #pragma unroll
            for (int i = 0; i < 4; i++) {
                int t = tn + 16 * i;
                float v = (acc[p][j][i] + be) * qscale;
                unsigned short hh, ll;
                fsplit(v, hh, ll);
                int idx = (p < 2) ? (t * 64 + e) : (e * 64 + t);
                sH[idx] = hh;
                sL[idx] = ll;
            }
        }
    }
    __syncthreads();

    #pragma unroll
    for (int p = 0; p < 3; p++) {
        unsigned short* sH = stg + p * 8192;
        unsigned short* sL = sH + 4096;
        unsigned short *Hd, *Ld;
        if (p == 0)      { Hd = g_Qh; Ld = g_Ql; }
        else if (p == 1) { Hd = g_Kh; Ld = g_Kl; }
        else             { Hd = g_Vh; Ld = g_Vl; }
        for (int i = tid; i < 512; i += 256) {
            int row = i >> 3, c8 = (i & 7) * 8;
            uint4 vh = reinterpret_cast<const uint4*>(sH)[i];
            uint4 vl = reinterpret_cast<const uint4*>(sL)[i];
            size_t off;
            if (p < 2) off = ((size_t)bh * TT + t0 + row) * DH + c8;
            else       off = ((size_t)bh * DH + row) * TT + t0 + c8;
            *reinterpret_cast<uint4*>(Hd + off) = vh;
            *reinterpret_cast<uint4*>(Ld + off) = vl;
        }
    }
}

// ---------------------------------------------------------------------------
// Kernel 2: flash attention via mma.sync + ldmatrix, cp.async double-buffer.
// 256 threads (8 warps, 16q each), grid (T/128, B*H).
// ---------------------------------------------------------------------------
#define ASTR 72
#define AQ_H 0
#define AQ_L (AQ_H + 128 * ASTR)
#define AKV  (AQ_L + 128 * ASTR)
#define AKV_STG (4 * 64 * ASTR)
#define A_MSK (AKV + 2 * AKV_STG)
#define ATTN_SMEM ((A_MSK + 1024) * 2)

__global__ __launch_bounds__(256) void attn_mma_kernel(const int* __restrict__ mask)
{
    extern __shared__ unsigned short shm[];
    int* sMask = (int*)(shm + A_MSK);
    uint32_t sb = (uint32_t)__cvta_generic_to_shared(shm);

    int tid = threadIdx.x;
    int wid = tid >> 5;
    int lane = tid & 31;
    int g = lane >> 2;
    int t = lane & 3;
    int wq = wid * 16;

    int bh = blockIdx.y;
    int b  = bh >> 4;
    int h  = bh & 15;
    int q0 = blockIdx.x * 128;

    // ldmatrix per-lane row terms
    int aRow  = (lane & 15);            // A-frag row within 16
    int aCol8 = (lane >> 4) * 8;        // A-frag k-half
    int bRow  = ((lane >> 4) & 1) * 8 + (lane & 7);   // B-frag row within pair
    int bCol8 = ((lane >> 3) & 1) * 8;                // B-frag k-half

    // load Q (regular loads) + mask
    {
        const unsigned short* Qhg = g_Qh + ((size_t)bh * TT + q0) * DH;
        const unsigned short* Qlg = g_Ql + ((size_t)bh * TT + q0) * DH;
        for (int i = tid; i < 1024; i += 256) {
            int row = i >> 3, c8 = (i & 7) * 8;
            *reinterpret_cast<uint4*>(&shm[AQ_H + row * ASTR + c8]) =
                *reinterpret_cast<const uint4*>(Qhg + row * DH + c8);
            *reinterpret_cast<uint4*>(&shm[AQ_L + row * ASTR + c8]) =
                *reinterpret_cast<const uint4*>(Qlg + row * DH + c8);
        }
        for (int i = tid; i < TT; i += 256) sMask[i] = mask[b * TT + i];
    }

    auto load_kv = [&](int stage, int kb) {
        unsigned short* stg = shm + AKV + stage * AKV_STG;
        for (int i = tid; i < 512; i += 256) {
            int row = i >> 3, c8 = (i & 7) * 8;
            size_t ko = ((size_t)bh * TT + kb + row) * DH + c8;
            size_t vo = ((size_t)bh * DH + row) * TT + kb + c8;
            cp16(stg + row * ASTR + c8,         g_Kh + ko);
            cp16(stg + 4608 + row * ASTR + c8,  g_Kl + ko);
            cp16(stg + 9216 + row * ASTR + c8,  g_Vh + vo);
            cp16(stg + 13824 + row * ASTR + c8, g_Vl + vo);
        }
    };
    load_kv(0, 0);
    CP_COMMIT();

    float O[8][4];
    float m_[2], l_[2];
    m_[0] = m_[1] = -1e30f;
    l_[0] = l_[1] = 0.0f;
    #pragma unroll
    for (int nt = 0; nt < 8; nt++)
        #pragma unroll
        for (int r = 0; r < 4; r++) O[nt][r] = 0.0f;

    uint32_t qBase = sb + 2 * (AQ_H + (wq + aRow) * ASTR + aCol8);

    for (int kt = 0; kt < 8; kt++) {
        int kb = kt * 64;
        if (kt + 1 < 8) load_kv((kt + 1) & 1, kb + 64);
        CP_COMMIT();
        CP_WAIT1();
        __syncthreads();

        uint32_t stgOff = 2 * (AKV + (kt & 1) * AKV_STG);
        uint32_t kBase = sb + stgOff + 2 * (bRow * ASTR + bCol8);
        uint32_t vBase = kBase + 2 * 9216;

        // ---- S = Q K^T (3-term split) ----
        float S[8][4];
        #pragma unroll
        for (int nt = 0; nt < 8; nt++)
            #pragma unroll
            for (int r = 0; r < 4; r++) S[nt][r] = 0.0f;

        #pragma unroll
        for (int ks = 0; ks < 4; ks++) {
            uint32_t qh[4], ql[4];
            ldm_x4(qh, qBase + 32 * ks);
            ldm_x4(ql, qBase + 32 * ks + 2 * (AQ_L - AQ_H));
            uint32_t kh[16], kl[16];
            #pragma unroll
            for (int p = 0; p < 4; p++) {
                ldm_x4(&kh[4 * p], kBase + 2 * (p * 16 * ASTR + ks * 16));
                ldm_x4(&kl[4 * p], kBase + 2 * (p * 16 * ASTR + ks * 16 + 4608));
            }
            #pragma unroll
            for (int nt = 0; nt < 8; nt++) {
                mma16816(S[nt], qh, &kh[2 * nt]);
                mma16816(S[nt], qh, &kl[2 * nt]);
                mma16816(S[nt], ql, &kh[2 * nt]);
            }
        }

        // ---- mask + online softmax ----
        #pragma unroll
        for (int nt = 0; nt < 8; nt++) {
            int mk0 = sMask[kb + nt * 8 + 2 * t];
            int mk1 = sMask[kb + nt * 8 + 2 * t + 1];
            if (mk0 <= 0) { S[nt][0] = -1e9f; S[nt][2] = -1e9f; }
            if (mk1 <= 0) { S[nt][1] = -1e9f; S[nt][3] = -1e9f; }
        }
        #pragma unroll
        for (int r = 0; r < 2; r++) {
            float mx = -1e30f;
            #pragma unroll
            for (int nt = 0; nt < 8; nt++) {
                mx = fmaxf(mx, S[nt][2 * r]);
                mx = fmaxf(mx, S[nt][2 * r + 1]);
            }
            mx = fmaxf(mx, __shfl_xor_sync(0xffffffffu, mx, 1));
            mx = fmaxf(mx, __shfl_xor_sync(0xffffffffu, mx, 2));
            float mnew  = fmaxf(m_[r], mx);
            float alpha = __expf(m_[r] - mnew);
            float rs = 0.0f;
            #pragma unroll
            for (int nt = 0; nt < 8; nt++) {
                float e0 = __expf(S[nt][2 * r]     - mnew);
                float e1 = __expf(S[nt][2 * r + 1] - mnew);
                S[nt][2 * r]     = e0;
                S[nt][2 * r + 1] = e1;
                rs += e0 + e1;
            }
            rs += __shfl_xor_sync(0xffffffffu, rs, 1);
            rs += __shfl_xor_sync(0xffffffffu, rs, 2);
            l_[r] = l_[r] * alpha + rs;
            m_[r] = mnew;
            #pragma unroll
            for (int nt = 0; nt < 8; nt++) {
                O[nt][2 * r]     *= alpha;
                O[nt][2 * r + 1] *= alpha;
            }
        }

        // ---- O += P V (3-term split) ----
        #pragma unroll
        for (int ks = 0; ks < 4; ks++) {
            uint32_t ph[4], pl[4];
            #pragma unroll
            for (int half = 0; half < 2; half++) {
                const float* sv = S[2 * ks + half];
                uint32_t b0 = __float_as_uint(sv[0]);
                uint32_t b1 = __float_as_uint(sv[1]);
                uint32_t b2 = __float_as_uint(sv[2]);
                uint32_t b3 = __float_as_uint(sv[3]);
                ph[2 * half]     = __byte_perm(b0, b1, 0x7632);
                ph[2 * half + 1] = __byte_perm(b2, b3, 0x7632);
                float l0 = sv[0] - __uint_as_float(b0 & 0xFFFF0000u);
                float l1 = sv[1] - __uint_as_float(b1 & 0xFFFF0000u);
                float l2 = sv[2] - __uint_as_float(b2 & 0xFFFF0000u);
                float l3 = sv[3] - __uint_as_float(b3 & 0xFFFF0000u);
                asm("cvt.rn.bf16x2.f32 %0, %1, %2;"
                    : "=r"(pl[2 * half]) : "f"(l1), "f"(l0));
                asm("cvt.rn.bf16x2.f32 %0, %1, %2;"
                    : "=r"(pl[2 * half + 1]) : "f"(l3), "f"(l2));
            }
            uint32_t vh[16], vl[16];
            #pragma unroll
            for (int p = 0; p < 4; p++) {
                ldm_x4(&vh[4 * p], vBase + 2 * (p * 16 * ASTR + ks * 16));
                ldm_x4(&vl[4 * p], vBase + 2 * (p * 16 * ASTR + ks * 16 + 4608));
            }
            #pragma unroll
            for (int nt = 0; nt < 8; nt++) {
                mma16816(O[nt], ph, &vh[2 * nt]);
                mma16816(O[nt], ph, &vl[2 * nt]);
                mma16816(O[nt], pl, &vh[2 * nt]);
            }
        }
        __syncthreads();
    }

    // epilogue: normalize, split to bf16 hi/lo, write g_Ah/g_Al
    #pragma unroll
    for (int r = 0; r < 2; r++) {
        float inv = 1.0f / l_[r];
        int mrow = b * TT + q0 + wq + g + 8 * r;
        size_t base = (size_t)mrow * DD + h * DH;
        #pragma unroll
        for (int nt = 0; nt < 8; nt++) {
            float v0 = O[nt][2 * r]     * inv;
            float v1 = O[nt][2 * r + 1] * inv;
            uint32_t b0 = __float_as_uint(v0), b1 = __float_as_uint(v1);
            uint32_t hp = __byte_perm(b0, b1, 0x7632);
            float l0 = v0 - __uint_as_float(b0 & 0xFFFF0000u);
            float l1 = v1 - __uint_as_float(b1 & 0xFFFF0000u);
            uint32_t lp;
            asm("cvt.rn.bf16x2.f32 %0, %1, %2;" : "=r"(lp) : "f"(l1), "f"(l0));
            *reinterpret_cast<uint32_t*>(g_Ah + base + nt * 8 + 2 * t) = hp;
            *reinterpret_cast<uint32_t*>(g_Al + base + nt * 8 + 2 * t) = lp;
        }
    }
}

// ---------------------------------------------------------------------------
// Kernel 3: Wf [k][n] fp32 -> g_Wh/g_Wl [n][k] bf16 (transpose + split)
// ---------------------------------------------------------------------------
__global__ __launch_bounds__(256) void convW_kernel(const float* __restrict__ Wf)
{
    __shared__ float t[32][33];
    int k0 = blockIdx.x * 32, n0 = blockIdx.y * 32;
    int tx = threadIdx.x & 31, ty = threadIdx.x >> 5;
    #pragma unroll
    for (int j = 0; j < 4; j++)
        t[ty + 8 * j][tx] = Wf[(size_t)(k0 + ty + 8 * j) * DD + n0 + tx];
    __syncthreads();
    #pragma unroll
    for (int j = 0; j < 4; j++) {
        int k = k0 + tx, n = n0 + ty + 8 * j;
        float v = t[tx][ty + 8 * j];
        unsigned short hh, ll;
        fsplit(v, hh, ll);
        g_Wh[(size_t)n * DD + k] = hh;
        g_Wl[(size_t)n * DD + k] = ll;
    }
}

// ---------------------------------------------------------------------------
// Kernel 4: fusion GEMM via mma.sync + ldmatrix, 3-stage cp.async, BK=32.
// CTA 128m x 64n, 8 warps (4m x 2n), warp 32m x 32n.
// ---------------------------------------------------------------------------
#define F2 40
#define FST_A  (128 * F2)
#define FST_B  (64 * F2)
#define FST_SZ (2 * FST_A + 2 * FST_B)
#define FNST 3
#define FUSE_SMEM (FNST * FST_SZ * 2)

__global__ __launch_bounds__(256, 2) void fuse_mma_kernel(
    const float* __restrict__ bf, float* __restrict__ C)
{
    extern __shared__ unsigned short fsm[];
    uint32_t sb = (uint32_t)__cvta_generic_to_shared(fsm);

    int tid = threadIdx.x;
    int wid = tid >> 5;
    int lane = tid & 31;
    int g = lane >> 2;
    int t = lane & 3;
    int wm = wid >> 1;
    int wn = wid & 1;

    int n0 = blockIdx.x * 64;
    int m0 = blockIdx.y * 128;

    int aRow  = (lane & 15);
    int aCol8 = (lane >> 4) * 8;
    int bRow  = ((lane >> 4) & 1) * 8 + (lane & 7);
    int bCol8 = ((lane >> 3) & 1) * 8;

    auto load_stage = [&](int stage, int k0) {
        unsigned short* st = fsm + stage * FST_SZ;
        for (int i = tid; i < 512; i += 256) {
            int row = i >> 2, c = (i & 3) * 8;
            size_t ga = (size_t)(m0 + row) * DD + k0 + c;
            cp16(st + row * F2 + c,          g_Ah + ga);
            cp16(st + FST_A + row * F2 + c,  g_Al + ga);
        }
        {
            int i = tid & 255;
            int row = i >> 2, c = (i & 3) * 8;
            size_t gb = (size_t)(n0 + row) * DD + k0 + c;
            cp16(st + 2 * FST_A + row * F2 + c,          g_Wh + gb);
            cp16(st + 2 * FST_A + FST_B + row * F2 + c,  g_Wl + gb);
        }
    };

    float acc[2][4][4];
    #pragma unroll
    for (int mt = 0; mt < 2; mt++)
        #pragma unroll
        for (int nt = 0; nt < 4; nt++)
            #pragma unroll
            for (int r = 0; r < 4; r++) acc[mt][nt][r] = 0.0f;

    load_stage(0, 0);
    CP_COMMIT();
    load_stage(1, 32);
    CP_COMMIT();

    uint32_t aBaseRow = 2 * ((wm * 32 + aRow) * F2 + aCol8);
    uint32_t bBaseRow = 2 * ((wn * 32 + bRow) * F2 + bCol8);

    for (int kt = 0; kt < 32; kt++) {
        CP_WAIT1();
        __syncthreads();

        uint32_t stOff = sb + (uint32_t)((kt % 3) * FST_SZ) * 2;

        #pragma unroll
        for (int ks = 0; ks < 2; ks++) {
            int k = ks * 16;
            uint32_t ah[2][4], al[2][4];
            #pragma unroll
            for (int mt = 0; mt < 2; mt++) {
                uint32_t ua = stOff + aBaseRow + 2 * (mt * 16 * F2 + k);
                ldm_x4(ah[mt], ua);
                ldm_x4(al[mt], ua + 2 * FST_A);
            }
            uint32_t bh[8], blo[8];
            #pragma unroll
            for (int p = 0; p < 2; p++) {
                uint32_t ub = stOff + bBaseRow + 2 * (2 * FST_A + p * 16 * F2 + k);
                ldm_x4(&bh[4 * p], ub);
                ldm_x4(&blo[4 * p], ub + 2 * FST_B);
            }
            #pragma unroll
            for (int mt = 0; mt < 2; mt++)
                #pragma unroll
                for (int nt = 0; nt < 4; nt++) {
                    mma16816(acc[mt][nt], ah[mt], &bh[2 * nt]);
                    mma16816(acc[mt][nt], ah[mt], &blo[2 * nt]);
                    mma16816(acc[mt][nt], al[mt], &bh[2 * nt]);
                }
        }
        __syncthreads();

        if (kt + 2 < 32) load_stage((kt + 2) % 3, (kt + 2) * 32);
        CP_COMMIT();
    }

    #pragma unroll
    for (int nt = 0; nt < 4; nt++) {
        int n = n0 + wn * 32 + nt * 8 + t * 2;
        float b0 = bf[n], b1 = bf[n + 1];
        #pragma unroll
        for (int mt = 0; mt < 2; mt++) {
            int m = m0 + wm * 32 + mt * 16 + g;
            float2 v0 = make_float2(acc[mt][nt][0] + b0, acc[mt][nt][1] + b1);
            float2 v1 = make_float2(acc[mt][nt][2] + b0, acc[mt][nt][3] + b1);
            *reinterpret_cast<float2*>(C + (size_t)m * DD + n) = v0;
            *reinterpret_cast<float2*>(C + (size_t)(m + 8) * DD + n) = v1;
        }
    }
}

// ---------------------------------------------------------------------------
extern "C" void kernel_launch(void* const* d_in, const int* in_sizes, int n_in,
                              void* d_out, int out_size)
{
    const float* X    = (const float*)d_in[0];
    const int*   mask = (const int*)  d_in[1];
    const float* Wq   = (const float*)d_in[2];
    const float* bq   = (const float*)d_in[3];
    const float* Wk   = (const float*)d_in[4];
    const float* bk   = (const float*)d_in[5];
    const float* Wv   = (const float*)d_in[6];
    const float* bv   = (const float*)d_in[7];
    const float* Wf   = (const float*)d_in[8];
    const float* bf   = (const float*)d_in[9];
    float* out = (float*)d_out;

    cudaFuncSetAttribute(qkv_kernel,
                         cudaFuncAttributeMaxDynamicSharedMemorySize, QKV_SMEM);
    cudaFuncSetAttribute(attn_mma_kernel,
                         cudaFuncAttributeMaxDynamicSharedMemorySize, ATTN_SMEM);
    cudaFuncSetAttribute(fuse_mma_kernel,
                         cudaFuncAttributeMaxDynamicSharedMemorySize, FUSE_SMEM);

    dim3 grid1(TT / 64, BB * HH);
    qkv_kernel<<<grid1, 256, QKV_SMEM>>>(X, Wq, bq, Wk, bk, Wv, bv);

    convW_kernel<<<dim3(32, 32), 256>>>(Wf);

    dim3 grid2(TT / 128, BB * HH);
    attn_mma_kernel<<<grid2, 256, ATTN_SMEM>>>(mask);

    dim3 grid4(DD / 64, (BB * TT) / 128);
    fuse_mma_kernel<<<grid4, 256, FUSE_SMEM>>>(bf, out);
}